// round 1
// baseline (speedup 1.0000x reference)
#include <cuda_runtime.h>

#define HID   4096
#define SEQ   2048
#define BATCH 2
#define NH    32
#define HD    128
#define MROWS (BATCH*SEQ)     /* 4096 */
#define NQKV  (3*HID)         /* 12288 */

// ---------------- scratch (device globals; no allocation APIs) -------------
__device__ float g_q[(size_t)BATCH*NH*SEQ*HD];     // [B,H,S,HD]
__device__ float g_k[(size_t)BATCH*NH*SEQ*HD];
__device__ float g_v[(size_t)BATCH*NH*SEQ*HD];
__device__ float g_ctx[(size_t)BATCH*SEQ*HID];     // [B,S,HID]

// ======================= Kernel 1: QKV GEMM + scatter ======================
// C[M=4096, N=12288] = X @ Wqkv + bqkv ; scatter to q/k/v [B,H,S,HD]
__global__ void __launch_bounds__(256, 2) gemm_qkv_kernel(
    const float* __restrict__ A, const float* __restrict__ W,
    const float* __restrict__ bias)
{
    const int K = HID, N = NQKV;
    __shared__ float As[2][8][128];   // transposed: As[k][m]
    __shared__ float Bs[2][8][128];   // Bs[k][n]

    const int tid = threadIdx.x;
    const int ty = tid >> 4, tx = tid & 15;
    const int m0 = blockIdx.y * 128, n0 = blockIdx.x * 128;
    const int ar = tid >> 1, ac = (tid & 1) * 4;
    const int br = tid >> 5, bc = (tid & 31) * 4;
    const float* Ap = A + (size_t)(m0 + ar) * K + ac;
    const float* Bp = W + (size_t)br * N + n0 + bc;

    float acc[8][8];
    #pragma unroll
    for (int i = 0; i < 8; i++)
        #pragma unroll
        for (int j = 0; j < 8; j++) acc[i][j] = 0.f;

    // prologue: tile 0
    {
        float4 av = *(const float4*)Ap;
        float4 bv = *(const float4*)Bp;
        As[0][ac+0][ar] = av.x; As[0][ac+1][ar] = av.y;
        As[0][ac+2][ar] = av.z; As[0][ac+3][ar] = av.w;
        *(float4*)&Bs[0][br][bc] = bv;
    }
    __syncthreads();

    const int NK = K / 8;
    for (int kt = 0; kt < NK; kt++) {
        const int cur = kt & 1;
        float4 av2, bv2;
        const bool more = (kt + 1 < NK);
        if (more) {
            av2 = *(const float4*)(Ap + (kt + 1) * 8);
            bv2 = *(const float4*)(Bp + (size_t)(kt + 1) * 8 * N);
        }
        #pragma unroll
        for (int kk = 0; kk < 8; kk++) {
            float a[8], b[8];
            #pragma unroll
            for (int i = 0; i < 8; i++) a[i] = As[cur][kk][ty + 16 * i];
            #pragma unroll
            for (int j = 0; j < 8; j++) b[j] = Bs[cur][kk][tx + 16 * j];
            #pragma unroll
            for (int i = 0; i < 8; i++)
                #pragma unroll
                for (int j = 0; j < 8; j++)
                    acc[i][j] = fmaf(a[i], b[j], acc[i][j]);
        }
        if (more) {
            const int nxt = cur ^ 1;
            As[nxt][ac+0][ar] = av2.x; As[nxt][ac+1][ar] = av2.y;
            As[nxt][ac+2][ar] = av2.z; As[nxt][ac+3][ar] = av2.w;
            *(float4*)&Bs[nxt][br][bc] = bv2;
        }
        __syncthreads();
    }

    // epilogue: +bias, scatter to [B,H,S,HD]
    #pragma unroll
    for (int i = 0; i < 8; i++) {
        const int row = m0 + ty + 16 * i;
        const int bb = row >> 11, ss = row & 2047;
        #pragma unroll
        for (int j = 0; j < 8; j++) {
            const int col = n0 + tx + 16 * j;
            float v = acc[i][j] + bias[col];
            const int h = col / 384;
            const int r = col - h * 384;
            const int comp = r >> 7, d = r & 127;
            float* dst = (comp == 0) ? g_q : (comp == 1) ? g_k : g_v;
            dst[((size_t)(bb * NH + h) * SEQ + ss) * HD + d] = v;
        }
    }
}

// ======================= Kernel 2: flash attention =========================
// smem: Qs[128][129] | Ks[128][129] (reused as Ps) | Vs[128][128]
#define ATT_SMEM ((128*129*2 + 128*128) * 4)

__global__ void __launch_bounds__(256, 1) attn_kernel(const float* __restrict__ alibi)
{
    extern __shared__ float sm[];
    float* Qs = sm;                 // stride 129
    float* Ks = sm + 128 * 129;     // stride 129 (later holds P)
    float* Vs = sm + 2 * 128 * 129; // stride 128

    const int tid = threadIdx.x;
    const int ty = tid >> 4, tx = tid & 15;
    const int qt = blockIdx.x;           // q tile
    const int bh = blockIdx.y;           // b*NH + h
    const int q0 = qt * 128;

    const float* qptr  = g_q + ((size_t)bh * SEQ + q0) * HD;
    const float* kbase = g_k + (size_t)bh * SEQ * HD;
    const float* vbase = g_v + (size_t)bh * SEQ * HD;
    const float* albase = alibi + (size_t)bh * SEQ;

    // load Q tile (128 x 128)
    for (int idx = tid; idx < 128 * 32; idx += 256) {
        const int r = idx >> 5, c = (idx & 31) * 4;
        float4 v = *(const float4*)(qptr + (size_t)r * HD + c);
        Qs[r * 129 + c + 0] = v.x; Qs[r * 129 + c + 1] = v.y;
        Qs[r * 129 + c + 2] = v.z; Qs[r * 129 + c + 3] = v.w;
    }

    float acc_o[8][8];
    float mrow[8], lrow[8];
    #pragma unroll
    for (int i = 0; i < 8; i++) {
        mrow[i] = -1e30f; lrow[i] = 0.f;
        #pragma unroll
        for (int j = 0; j < 8; j++) acc_o[i][j] = 0.f;
    }
    const float inv_norm = 0.088388347648318447f;  // 1/sqrt(128)

    for (int kt = 0; kt <= qt; kt++) {
        const int k0 = kt * 128;
        __syncthreads();  // prev PV done; Q load visible on first iter

        for (int idx = tid; idx < 128 * 32; idx += 256) {
            const int r = idx >> 5, c = (idx & 31) * 4;
            float4 kv = *(const float4*)(kbase + (size_t)(k0 + r) * HD + c);
            Ks[r * 129 + c + 0] = kv.x; Ks[r * 129 + c + 1] = kv.y;
            Ks[r * 129 + c + 2] = kv.z; Ks[r * 129 + c + 3] = kv.w;
            float4 vv = *(const float4*)(vbase + (size_t)(k0 + r) * HD + c);
            *(float4*)&Vs[r * 128 + c] = vv;
        }
        __syncthreads();

        // S = Q @ K^T  (reduce over d)
        float s[8][8];
        #pragma unroll
        for (int i = 0; i < 8; i++)
            #pragma unroll
            for (int j = 0; j < 8; j++) s[i][j] = 0.f;
        for (int d = 0; d < 128; d++) {
            float a[8], b[8];
            #pragma unroll
            for (int i = 0; i < 8; i++) a[i] = Qs[(ty + 16 * i) * 129 + d];
            #pragma unroll
            for (int j = 0; j < 8; j++) b[j] = Ks[(tx + 16 * j) * 129 + d];
            #pragma unroll
            for (int i = 0; i < 8; i++)
                #pragma unroll
                for (int j = 0; j < 8; j++)
                    s[i][j] = fmaf(a[i], b[j], s[i][j]);
        }

        // alibi (depends only on key position)
        float al[8];
        #pragma unroll
        for (int j = 0; j < 8; j++) al[j] = __ldg(albase + k0 + tx + 16 * j);

        const bool diag = (kt == qt);
        #pragma unroll
        for (int i = 0; i < 8; i++) {
            const int qg = q0 + ty + 16 * i;
            float mx = -1e30f;
            #pragma unroll
            for (int j = 0; j < 8; j++) {
                float v = s[i][j] * inv_norm + al[j];
                if (diag && (k0 + tx + 16 * j) > qg) v = -1e30f;
                s[i][j] = v;
                mx = fmaxf(mx, v);
            }
            mx = fmaxf(mx, __shfl_xor_sync(0xffffffffu, mx, 1));
            mx = fmaxf(mx, __shfl_xor_sync(0xffffffffu, mx, 2));
            mx = fmaxf(mx, __shfl_xor_sync(0xffffffffu, mx, 4));
            mx = fmaxf(mx, __shfl_xor_sync(0xffffffffu, mx, 8));
            const float mnew = fmaxf(mrow[i], mx);
            const float corr = __expf(mrow[i] - mnew);
            float ls = 0.f;
            #pragma unroll
            for (int j = 0; j < 8; j++) {
                float p = __expf(s[i][j] - mnew);
                s[i][j] = p;
                ls += p;
            }
            ls += __shfl_xor_sync(0xffffffffu, ls, 1);
            ls += __shfl_xor_sync(0xffffffffu, ls, 2);
            ls += __shfl_xor_sync(0xffffffffu, ls, 4);
            ls += __shfl_xor_sync(0xffffffffu, ls, 8);
            lrow[i] = lrow[i] * corr + ls;
            mrow[i] = mnew;
            #pragma unroll
            for (int j = 0; j < 8; j++) acc_o[i][j] *= corr;
        }

        __syncthreads();  // everyone done reading Ks
        #pragma unroll
        for (int i = 0; i < 8; i++)
            #pragma unroll
            for (int j = 0; j < 8; j++)
                Ks[(ty + 16 * i) * 129 + (tx + 16 * j)] = s[i][j];  // P
        __syncthreads();

        // O += P @ V  (reduce over key)
        for (int kk = 0; kk < 128; kk++) {
            float a[8], b[8];
            #pragma unroll
            for (int i = 0; i < 8; i++) a[i] = Ks[(ty + 16 * i) * 129 + kk];
            #pragma unroll
            for (int j = 0; j < 8; j++) b[j] = Vs[kk * 128 + tx + 16 * j];
            #pragma unroll
            for (int i = 0; i < 8; i++)
                #pragma unroll
                for (int j = 0; j < 8; j++)
                    acc_o[i][j] = fmaf(a[i], b[j], acc_o[i][j]);
        }
    }

    // epilogue: divide by l, write ctx[b, s, h*HD + d]
    const int b = bh >> 5, h = bh & 31;
    #pragma unroll
    for (int i = 0; i < 8; i++) {
        const float invl = 1.f / lrow[i];
        const int srow = q0 + ty + 16 * i;
        float* op = g_ctx + ((size_t)(b * SEQ + srow)) * HID + h * HD;
        #pragma unroll
        for (int j = 0; j < 8; j++)
            op[tx + 16 * j] = acc_o[i][j] * invl;
    }
}

// =================== Kernel 3: output GEMM + bias + residual ===============
__global__ void __launch_bounds__(256, 2) gemm_out_kernel(
    const float* __restrict__ resid, const float* __restrict__ W,
    const float* __restrict__ bias, float* __restrict__ out)
{
    const int K = HID, N = HID;
    __shared__ float As[2][8][128];
    __shared__ float Bs[2][8][128];

    const int tid = threadIdx.x;
    const int ty = tid >> 4, tx = tid & 15;
    const int m0 = blockIdx.y * 128, n0 = blockIdx.x * 128;
    const int ar = tid >> 1, ac = (tid & 1) * 4;
    const int br = tid >> 5, bc = (tid & 31) * 4;
    const float* Ap = g_ctx + (size_t)(m0 + ar) * K + ac;
    const float* Bp = W + (size_t)br * N + n0 + bc;

    float acc[8][8];
    #pragma unroll
    for (int i = 0; i < 8; i++)
        #pragma unroll
        for (int j = 0; j < 8; j++) acc[i][j] = 0.f;

    {
        float4 av = *(const float4*)Ap;
        float4 bv = *(const float4*)Bp;
        As[0][ac+0][ar] = av.x; As[0][ac+1][ar] = av.y;
        As[0][ac+2][ar] = av.z; As[0][ac+3][ar] = av.w;
        *(float4*)&Bs[0][br][bc] = bv;
    }
    __syncthreads();

    const int NK = K / 8;
    for (int kt = 0; kt < NK; kt++) {
        const int cur = kt & 1;
        float4 av2, bv2;
        const bool more = (kt + 1 < NK);
        if (more) {
            av2 = *(const float4*)(Ap + (kt + 1) * 8);
            bv2 = *(const float4*)(Bp + (size_t)(kt + 1) * 8 * N);
        }
        #pragma unroll
        for (int kk = 0; kk < 8; kk++) {
            float a[8], b[8];
            #pragma unroll
            for (int i = 0; i < 8; i++) a[i] = As[cur][kk][ty + 16 * i];
            #pragma unroll
            for (int j = 0; j < 8; j++) b[j] = Bs[cur][kk][tx + 16 * j];
            #pragma unroll
            for (int i = 0; i < 8; i++)
                #pragma unroll
                for (int j = 0; j < 8; j++)
                    acc[i][j] = fmaf(a[i], b[j], acc[i][j]);
        }
        if (more) {
            const int nxt = cur ^ 1;
            As[nxt][ac+0][ar] = av2.x; As[nxt][ac+1][ar] = av2.y;
            As[nxt][ac+2][ar] = av2.z; As[nxt][ac+3][ar] = av2.w;
            *(float4*)&Bs[nxt][br][bc] = bv2;
        }
        __syncthreads();
    }

    #pragma unroll
    for (int i = 0; i < 8; i++) {
        const int row = m0 + ty + 16 * i;
        #pragma unroll
        for (int j = 0; j < 8; j++) {
            const int col = n0 + tx + 16 * j;
            const size_t o = (size_t)row * HID + col;
            out[o] = acc[i][j] + bias[col] + resid[o];
        }
    }
}

// =============================== launch ====================================
extern "C" void kernel_launch(void* const* d_in, const int* in_sizes, int n_in,
                              void* d_out, int out_size)
{
    const float* hs    = (const float*)d_in[0];
    const float* resid = (const float*)d_in[1];
    const float* alibi = (const float*)d_in[2];
    // d_in[3] = attention_mask (causal, reconstructed analytically)
    const float* Wqkv  = (const float*)d_in[4];
    const float* bqkv  = (const float*)d_in[5];
    const float* Wd    = (const float*)d_in[6];
    const float* bd    = (const float*)d_in[7];
    float* out = (float*)d_out;

    cudaFuncSetAttribute(attn_kernel,
                         cudaFuncAttributeMaxDynamicSharedMemorySize, ATT_SMEM);

    gemm_qkv_kernel<<<dim3(NQKV / 128, MROWS / 128), 256>>>(hs, Wqkv, bqkv);
    attn_kernel<<<dim3(SEQ / 128, BATCH * NH), 256, ATT_SMEM>>>(alibi);
    gemm_out_kernel<<<dim3(HID / 128, MROWS / 128), 256>>>(resid, Wd, bd, out);
}

// round 2
// speedup vs baseline: 1.0016x; 1.0016x over previous
#include <cuda_runtime.h>

#define HID   4096
#define SEQ   2048
#define BATCH 2
#define NH    32
#define HD    128
#define MROWS (BATCH*SEQ)     /* 4096 */
#define NQKV  (3*HID)         /* 12288 */

// ---------------- scratch (device globals; no allocation APIs) -------------
__device__ float g_q[(size_t)BATCH*NH*SEQ*HD];     // [B,H,S,HD]
__device__ float g_k[(size_t)BATCH*NH*SEQ*HD];
__device__ float g_v[(size_t)BATCH*NH*SEQ*HD];
__device__ float g_ctx[(size_t)BATCH*SEQ*HID];     // [B,S,HID]

// ======================= Kernel 1: QKV GEMM + scatter ======================
// C[M=4096, N=12288] = X @ Wqkv + bqkv ; scatter to q/k/v [B,H,S,HD]
__global__ void __launch_bounds__(256, 2) gemm_qkv_kernel(
    const float* __restrict__ A, const float* __restrict__ W,
    const float* __restrict__ bias)
{
    const int K = HID, N = NQKV;
    __shared__ float As[2][8][128];   // transposed: As[k][m]
    __shared__ float Bs[2][8][128];   // Bs[k][n]

    const int tid = threadIdx.x;
    const int ty = tid >> 4, tx = tid & 15;
    const int m0 = blockIdx.y * 128, n0 = blockIdx.x * 128;
    const int ar = tid >> 1, ac = (tid & 1) * 4;
    const int br = tid >> 5, bc = (tid & 31) * 4;
    const float* Ap = A + (size_t)(m0 + ar) * K + ac;
    const float* Bp = W + (size_t)br * N + n0 + bc;

    float acc[8][8];
    #pragma unroll
    for (int i = 0; i < 8; i++)
        #pragma unroll
        for (int j = 0; j < 8; j++) acc[i][j] = 0.f;

    // prologue: tile 0
    {
        float4 av = *(const float4*)Ap;
        float4 bv = *(const float4*)Bp;
        As[0][ac+0][ar] = av.x; As[0][ac+1][ar] = av.y;
        As[0][ac+2][ar] = av.z; As[0][ac+3][ar] = av.w;
        *(float4*)&Bs[0][br][bc] = bv;
    }
    __syncthreads();

    const int NK = K / 8;
    for (int kt = 0; kt < NK; kt++) {
        const int cur = kt & 1;
        float4 av2, bv2;
        const bool more = (kt + 1 < NK);
        if (more) {
            av2 = *(const float4*)(Ap + (kt + 1) * 8);
            bv2 = *(const float4*)(Bp + (size_t)(kt + 1) * 8 * N);
        }
        #pragma unroll
        for (int kk = 0; kk < 8; kk++) {
            float a[8], b[8];
            #pragma unroll
            for (int i = 0; i < 8; i++) a[i] = As[cur][kk][ty + 16 * i];
            #pragma unroll
            for (int j = 0; j < 8; j++) b[j] = Bs[cur][kk][tx + 16 * j];
            #pragma unroll
            for (int i = 0; i < 8; i++)
                #pragma unroll
                for (int j = 0; j < 8; j++)
                    acc[i][j] = fmaf(a[i], b[j], acc[i][j]);
        }
        if (more) {
            const int nxt = cur ^ 1;
            As[nxt][ac+0][ar] = av2.x; As[nxt][ac+1][ar] = av2.y;
            As[nxt][ac+2][ar] = av2.z; As[nxt][ac+3][ar] = av2.w;
            *(float4*)&Bs[nxt][br][bc] = bv2;
        }
        __syncthreads();
    }

    // epilogue: +bias, scatter to [B,H,S,HD]
    #pragma unroll
    for (int i = 0; i < 8; i++) {
        const int row = m0 + ty + 16 * i;
        const int bb = row >> 11, ss = row & 2047;
        #pragma unroll
        for (int j = 0; j < 8; j++) {
            const int col = n0 + tx + 16 * j;
            float v = acc[i][j] + bias[col];
            const int h = col / 384;
            const int r = col - h * 384;
            const int comp = r >> 7, d = r & 127;
            float* dst = (comp == 0) ? g_q : (comp == 1) ? g_k : g_v;
            dst[((size_t)(bb * NH + h) * SEQ + ss) * HD + d] = v;
        }
    }
}

// ======================= Kernel 2: flash attention =========================
// smem: Qs[128][129] | Ks[128][129] (reused as Ps) | Vs[128][128]
#define ATT_SMEM ((128*129*2 + 128*128) * 4)

__global__ void __launch_bounds__(256, 1) attn_kernel(const float* __restrict__ alibi)
{
    extern __shared__ float sm[];
    float* Qs = sm;                 // stride 129
    float* Ks = sm + 128 * 129;     // stride 129 (later holds P)
    float* Vs = sm + 2 * 128 * 129; // stride 128

    const int tid = threadIdx.x;
    const int ty = tid >> 4, tx = tid & 15;
    const int qt = blockIdx.x;           // q tile
    const int bh = blockIdx.y;           // b*NH + h
    const int q0 = qt * 128;

    const float* qptr  = g_q + ((size_t)bh * SEQ + q0) * HD;
    const float* kbase = g_k + (size_t)bh * SEQ * HD;
    const float* vbase = g_v + (size_t)bh * SEQ * HD;
    const float* albase = alibi + (size_t)bh * SEQ;

    // load Q tile (128 x 128)
    for (int idx = tid; idx < 128 * 32; idx += 256) {
        const int r = idx >> 5, c = (idx & 31) * 4;
        float4 v = *(const float4*)(qptr + (size_t)r * HD + c);
        Qs[r * 129 + c + 0] = v.x; Qs[r * 129 + c + 1] = v.y;
        Qs[r * 129 + c + 2] = v.z; Qs[r * 129 + c + 3] = v.w;
    }

    float acc_o[8][8];
    float mrow[8], lrow[8];
    #pragma unroll
    for (int i = 0; i < 8; i++) {
        mrow[i] = -1e30f; lrow[i] = 0.f;
        #pragma unroll
        for (int j = 0; j < 8; j++) acc_o[i][j] = 0.f;
    }
    const float inv_norm = 0.088388347648318447f;  // 1/sqrt(128)

    for (int kt = 0; kt <= qt; kt++) {
        const int k0 = kt * 128;
        __syncthreads();  // prev PV done; Q load visible on first iter

        for (int idx = tid; idx < 128 * 32; idx += 256) {
            const int r = idx >> 5, c = (idx & 31) * 4;
            float4 kv = *(const float4*)(kbase + (size_t)(k0 + r) * HD + c);
            Ks[r * 129 + c + 0] = kv.x; Ks[r * 129 + c + 1] = kv.y;
            Ks[r * 129 + c + 2] = kv.z; Ks[r * 129 + c + 3] = kv.w;
            float4 vv = *(const float4*)(vbase + (size_t)(k0 + r) * HD + c);
            *(float4*)&Vs[r * 128 + c] = vv;
        }
        __syncthreads();

        // S = Q @ K^T  (reduce over d)
        float s[8][8];
        #pragma unroll
        for (int i = 0; i < 8; i++)
            #pragma unroll
            for (int j = 0; j < 8; j++) s[i][j] = 0.f;
        for (int d = 0; d < 128; d++) {
            float a[8], b[8];
            #pragma unroll
            for (int i = 0; i < 8; i++) a[i] = Qs[(ty + 16 * i) * 129 + d];
            #pragma unroll
            for (int j = 0; j < 8; j++) b[j] = Ks[(tx + 16 * j) * 129 + d];
            #pragma unroll
            for (int i = 0; i < 8; i++)
                #pragma unroll
                for (int j = 0; j < 8; j++)
                    s[i][j] = fmaf(a[i], b[j], s[i][j]);
        }

        // alibi (depends only on key position)
        float al[8];
        #pragma unroll
        for (int j = 0; j < 8; j++) al[j] = __ldg(albase + k0 + tx + 16 * j);

        const bool diag = (kt == qt);
        #pragma unroll
        for (int i = 0; i < 8; i++) {
            const int qg = q0 + ty + 16 * i;
            float mx = -1e30f;
            #pragma unroll
            for (int j = 0; j < 8; j++) {
                float v = s[i][j] * inv_norm + al[j];
                if (diag && (k0 + tx + 16 * j) > qg) v = -1e30f;
                s[i][j] = v;
                mx = fmaxf(mx, v);
            }
            mx = fmaxf(mx, __shfl_xor_sync(0xffffffffu, mx, 1));
            mx = fmaxf(mx, __shfl_xor_sync(0xffffffffu, mx, 2));
            mx = fmaxf(mx, __shfl_xor_sync(0xffffffffu, mx, 4));
            mx = fmaxf(mx, __shfl_xor_sync(0xffffffffu, mx, 8));
            const float mnew = fmaxf(mrow[i], mx);
            const float corr = __expf(mrow[i] - mnew);
            float ls = 0.f;
            #pragma unroll
            for (int j = 0; j < 8; j++) {
                float p = __expf(s[i][j] - mnew);
                s[i][j] = p;
                ls += p;
            }
            ls += __shfl_xor_sync(0xffffffffu, ls, 1);
            ls += __shfl_xor_sync(0xffffffffu, ls, 2);
            ls += __shfl_xor_sync(0xffffffffu, ls, 4);
            ls += __shfl_xor_sync(0xffffffffu, ls, 8);
            lrow[i] = lrow[i] * corr + ls;
            mrow[i] = mnew;
            #pragma unroll
            for (int j = 0; j < 8; j++) acc_o[i][j] *= corr;
        }

        __syncthreads();  // everyone done reading Ks
        #pragma unroll
        for (int i = 0; i < 8; i++)
            #pragma unroll
            for (int j = 0; j < 8; j++)
                Ks[(ty + 16 * i) * 129 + (tx + 16 * j)] = s[i][j];  // P
        __syncthreads();

        // O += P @ V  (reduce over key)
        for (int kk = 0; kk < 128; kk++) {
            float a[8], b[8];
            #pragma unroll
            for (int i = 0; i < 8; i++) a[i] = Ks[(ty + 16 * i) * 129 + kk];
            #pragma unroll
            for (int j = 0; j < 8; j++) b[j] = Vs[kk * 128 + tx + 16 * j];
            #pragma unroll
            for (int i = 0; i < 8; i++)
                #pragma unroll
                for (int j = 0; j < 8; j++)
                    acc_o[i][j] = fmaf(a[i], b[j], acc_o[i][j]);
        }
    }

    // epilogue: divide by l, write ctx[b, s, h*HD + d]
    const int b = bh >> 5, h = bh & 31;
    #pragma unroll
    for (int i = 0; i < 8; i++) {
        const float invl = 1.f / lrow[i];
        const int srow = q0 + ty + 16 * i;
        float* op = g_ctx + ((size_t)(b * SEQ + srow)) * HID + h * HD;
        #pragma unroll
        for (int j = 0; j < 8; j++)
            op[tx + 16 * j] = acc_o[i][j] * invl;
    }
}

// =================== Kernel 3: output GEMM + bias + residual ===============
__global__ void __launch_bounds__(256, 2) gemm_out_kernel(
    const float* __restrict__ resid, const float* __restrict__ W,
    const float* __restrict__ bias, float* __restrict__ out)
{
    const int K = HID, N = HID;
    __shared__ float As[2][8][128];
    __shared__ float Bs[2][8][128];

    const int tid = threadIdx.x;
    const int ty = tid >> 4, tx = tid & 15;
    const int m0 = blockIdx.y * 128, n0 = blockIdx.x * 128;
    const int ar = tid >> 1, ac = (tid & 1) * 4;
    const int br = tid >> 5, bc = (tid & 31) * 4;
    const float* Ap = g_ctx + (size_t)(m0 + ar) * K + ac;
    const float* Bp = W + (size_t)br * N + n0 + bc;

    float acc[8][8];
    #pragma unroll
    for (int i = 0; i < 8; i++)
        #pragma unroll
        for (int j = 0; j < 8; j++) acc[i][j] = 0.f;

    {
        float4 av = *(const float4*)Ap;
        float4 bv = *(const float4*)Bp;
        As[0][ac+0][ar] = av.x; As[0][ac+1][ar] = av.y;
        As[0][ac+2][ar] = av.z; As[0][ac+3][ar] = av.w;
        *(float4*)&Bs[0][br][bc] = bv;
    }
    __syncthreads();

    const int NK = K / 8;
    for (int kt = 0; kt < NK; kt++) {
        const int cur = kt & 1;
        float4 av2, bv2;
        const bool more = (kt + 1 < NK);
        if (more) {
            av2 = *(const float4*)(Ap + (kt + 1) * 8);
            bv2 = *(const float4*)(Bp + (size_t)(kt + 1) * 8 * N);
        }
        #pragma unroll
        for (int kk = 0; kk < 8; kk++) {
            float a[8], b[8];
            #pragma unroll
            for (int i = 0; i < 8; i++) a[i] = As[cur][kk][ty + 16 * i];
            #pragma unroll
            for (int j = 0; j < 8; j++) b[j] = Bs[cur][kk][tx + 16 * j];
            #pragma unroll
            for (int i = 0; i < 8; i++)
                #pragma unroll
                for (int j = 0; j < 8; j++)
                    acc[i][j] = fmaf(a[i], b[j], acc[i][j]);
        }
        if (more) {
            const int nxt = cur ^ 1;
            As[nxt][ac+0][ar] = av2.x; As[nxt][ac+1][ar] = av2.y;
            As[nxt][ac+2][ar] = av2.z; As[nxt][ac+3][ar] = av2.w;
            *(float4*)&Bs[nxt][br][bc] = bv2;
        }
        __syncthreads();
    }

    #pragma unroll
    for (int i = 0; i < 8; i++) {
        const int row = m0 + ty + 16 * i;
        #pragma unroll
        for (int j = 0; j < 8; j++) {
            const int col = n0 + tx + 16 * j;
            const size_t o = (size_t)row * HID + col;
            out[o] = acc[i][j] + bias[col] + resid[o];
        }
    }
}

// =============================== launch ====================================
extern "C" void kernel_launch(void* const* d_in, const int* in_sizes, int n_in,
                              void* d_out, int out_size)
{
    const float* hs    = (const float*)d_in[0];
    const float* resid = (const float*)d_in[1];
    const float* alibi = (const float*)d_in[2];
    // d_in[3] = attention_mask (causal, reconstructed analytically)
    const float* Wqkv  = (const float*)d_in[4];
    const float* bqkv  = (const float*)d_in[5];
    const float* Wd    = (const float*)d_in[6];
    const float* bd    = (const float*)d_in[7];
    float* out = (float*)d_out;

    cudaFuncSetAttribute(attn_kernel,
                         cudaFuncAttributeMaxDynamicSharedMemorySize, ATT_SMEM);

    gemm_qkv_kernel<<<dim3(NQKV / 128, MROWS / 128), 256>>>(hs, Wqkv, bqkv);
    attn_kernel<<<dim3(SEQ / 128, BATCH * NH), 256, ATT_SMEM>>>(alibi);
    gemm_out_kernel<<<dim3(HID / 128, MROWS / 128), 256>>>(resid, Wd, bd, out);
}

// round 4
// speedup vs baseline: 2.0114x; 2.0082x over previous
#include <cuda_runtime.h>
#include <cuda_bf16.h>
#include <stdint.h>

#define HID   4096
#define SEQ   2048
#define BATCH 2
#define NH    32
#define HD    128
#define MROWS (BATCH*SEQ)
#define NQKV  (3*HID)

__device__ float g_q[(size_t)BATCH*NH*SEQ*HD];
__device__ float g_k[(size_t)BATCH*NH*SEQ*HD];
__device__ float g_v[(size_t)BATCH*NH*SEQ*HD];
__device__ float g_ctx[(size_t)BATCH*SEQ*HID];

// ============================ helpers ======================================
__device__ __forceinline__ uint32_t smem_u32(const void* p) {
    uint32_t a;
    asm("{ .reg .u64 t; cvta.to.shared.u64 t, %1; cvt.u32.u64 %0, t; }" : "=r"(a) : "l"(p));
    return a;
}
__device__ __forceinline__ void ldsm4(uint32_t* r, uint32_t addr) {
    asm volatile("ldmatrix.sync.aligned.m8n8.x4.shared.b16 {%0,%1,%2,%3}, [%4];"
                 : "=r"(r[0]), "=r"(r[1]), "=r"(r[2]), "=r"(r[3]) : "r"(addr));
}
__device__ __forceinline__ void mma16816(float* d, const uint32_t* a, const uint32_t* b) {
    asm volatile("mma.sync.aligned.m16n8k16.row.col.f32.bf16.bf16.f32 "
                 "{%0,%1,%2,%3}, {%4,%5,%6,%7}, {%8,%9}, {%0,%1,%2,%3};"
                 : "+f"(d[0]), "+f"(d[1]), "+f"(d[2]), "+f"(d[3])
                 : "r"(a[0]), "r"(a[1]), "r"(a[2]), "r"(a[3]), "r"(b[0]), "r"(b[1]));
}
__device__ __forceinline__ void split_pack(float a, float b, uint32_t& h, uint32_t& l) {
    __nv_bfloat162 hb = __floats2bfloat162_rn(a, b);
    float la = a - __bfloat162float(hb.x);
    float lb = b - __bfloat162float(hb.y);
    __nv_bfloat162 lo2 = __floats2bfloat162_rn(la, lb);
    h = *(uint32_t*)&hb; l = *(uint32_t*)&lo2;
}

// stage layout (bytes): Ah@0, Al@10240, Bh@20480, Bl@30720 ; 80B row stride
#define ROWB   80
#define PLANE  10240
#define STAGE  40960
#define GEMM_SMEM (2 * STAGE)

// =============== mma.sync bf16x3 GEMM: C[128,128] tile per CTA =============
template <bool IS_QKV>
__global__ void __launch_bounds__(256, 1)
gemm_mma_kernel(const float* __restrict__ Ain, const float* __restrict__ W,
                const float* __restrict__ bias, const float* __restrict__ resid,
                float* __restrict__ out)
{
    constexpr int N  = IS_QKV ? NQKV : HID;
    constexpr int NC = HID / 32;              // 128 K-chunks
    extern __shared__ __align__(16) char stg[];
    const uint32_t stg_u = smem_u32(stg);

    const float* A = IS_QKV ? Ain : (const float*)g_ctx;
    const int tid  = threadIdx.x;
    const int wid  = tid >> 5, lane = tid & 31;
    const int wm   = wid >> 1, wn = wid & 1;  // 4x2 warp grid, warp tile 32x64
    const int m0   = blockIdx.y * 128, n0 = blockIdx.x * 128;

    // loader roles
    const int arow = tid >> 1, akh = tid & 1;            // A: row, k-half(16)
    const int bn   = tid & 127, bkh = tid >> 7;          // B: n, k-half(16)
    const float* apg = A + (size_t)(m0 + arow) * HID + akh * 16;
    const float* wpg = W + (size_t)(bkh * 16) * N + n0 + bn;

    float acc[2][8][4];
    #pragma unroll
    for (int mi = 0; mi < 2; mi++)
        #pragma unroll
        for (int nj = 0; nj < 8; nj++)
            #pragma unroll
            for (int r = 0; r < 4; r++) acc[mi][nj][r] = 0.f;

    float4 pa[4];
    float  pb[16];

    // ldmatrix base addresses (per buffer add cur*STAGE)
    const uint32_t a_base = stg_u + (uint32_t)(wm * 32 + (lane & 15)) * ROWB + ((lane >> 4) << 4);
    const uint32_t b_base = stg_u + 20480u
                          + (uint32_t)(wn * 64 + (lane & 7) + ((lane >> 4) << 3)) * ROWB
                          + (((lane >> 3) & 1) << 4);

    // ---- prologue: load chunk 0 straight to smem ----
    {
        const float* ap = apg;
        float4 q0 = *(const float4*)ap, q1 = *(const float4*)(ap + 4);
        float4 q2 = *(const float4*)(ap + 8), q3 = *(const float4*)(ap + 12);
        uint32_t h[8], l[8];
        split_pack(q0.x,q0.y,h[0],l[0]); split_pack(q0.z,q0.w,h[1],l[1]);
        split_pack(q1.x,q1.y,h[2],l[2]); split_pack(q1.z,q1.w,h[3],l[3]);
        split_pack(q2.x,q2.y,h[4],l[4]); split_pack(q2.z,q2.w,h[5],l[5]);
        split_pack(q3.x,q3.y,h[6],l[6]); split_pack(q3.z,q3.w,h[7],l[7]);
        char* pa0 = stg + arow * ROWB + akh * 32;
        *(uint4*)pa0           = make_uint4(h[0],h[1],h[2],h[3]);
        *(uint4*)(pa0 + 16)    = make_uint4(h[4],h[5],h[6],h[7]);
        *(uint4*)(pa0 + PLANE) = make_uint4(l[0],l[1],l[2],l[3]);
        *(uint4*)(pa0 + PLANE + 16) = make_uint4(l[4],l[5],l[6],l[7]);
        float f[16];
        #pragma unroll
        for (int j = 0; j < 16; j++) f[j] = __ldg(wpg + (size_t)j * N);
        split_pack(f[0],f[1],h[0],l[0]);  split_pack(f[2],f[3],h[1],l[1]);
        split_pack(f[4],f[5],h[2],l[2]);  split_pack(f[6],f[7],h[3],l[3]);
        split_pack(f[8],f[9],h[4],l[4]);  split_pack(f[10],f[11],h[5],l[5]);
        split_pack(f[12],f[13],h[6],l[6]);split_pack(f[14],f[15],h[7],l[7]);
        char* pb0 = stg + 20480 + bn * ROWB + bkh * 32;
        *(uint4*)pb0           = make_uint4(h[0],h[1],h[2],h[3]);
        *(uint4*)(pb0 + 16)    = make_uint4(h[4],h[5],h[6],h[7]);
        *(uint4*)(pb0 + PLANE) = make_uint4(l[0],l[1],l[2],l[3]);
        *(uint4*)(pb0 + PLANE + 16) = make_uint4(l[4],l[5],l[6],l[7]);
    }
    __syncthreads();

    for (int c = 0; c < NC; c++) {
        const int cur = c & 1;
        const bool more = (c + 1 < NC);
        if (more) {  // prefetch chunk c+1 into registers
            const int k0 = (c + 1) * 32;
            const float* ap = apg + k0;
            pa[0] = *(const float4*)ap;       pa[1] = *(const float4*)(ap + 4);
            pa[2] = *(const float4*)(ap + 8); pa[3] = *(const float4*)(ap + 12);
            const float* wp = wpg + (size_t)k0 * N;
            #pragma unroll
            for (int j = 0; j < 16; j++) pb[j] = __ldg(wp + (size_t)j * N);
        }

        // ---- compute on cur ----
        const uint32_t ab = a_base + cur * STAGE;
        const uint32_t bb = b_base + cur * STAGE;
        #pragma unroll
        for (int kk = 0; kk < 2; kk++) {
            uint32_t aH[2][4], aL[2][4], bF[4][4];
            ldsm4(aH[0], ab + kk * 32);
            ldsm4(aH[1], ab + kk * 32 + 16 * ROWB);
            ldsm4(aL[0], ab + PLANE + kk * 32);
            ldsm4(aL[1], ab + PLANE + kk * 32 + 16 * ROWB);
            #pragma unroll
            for (int j2 = 0; j2 < 4; j2++) ldsm4(bF[j2], bb + kk * 32 + j2 * 16 * ROWB);
            #pragma unroll
            for (int mi = 0; mi < 2; mi++)
                #pragma unroll
                for (int j2 = 0; j2 < 4; j2++) {
                    mma16816(acc[mi][2*j2],   aH[mi], &bF[j2][0]);
                    mma16816(acc[mi][2*j2+1], aH[mi], &bF[j2][2]);
                }
            #pragma unroll
            for (int mi = 0; mi < 2; mi++)
                #pragma unroll
                for (int j2 = 0; j2 < 4; j2++) {
                    mma16816(acc[mi][2*j2],   aL[mi], &bF[j2][0]);
                    mma16816(acc[mi][2*j2+1], aL[mi], &bF[j2][2]);
                }
            #pragma unroll
            for (int j2 = 0; j2 < 4; j2++) ldsm4(bF[j2], bb + PLANE + kk * 32 + j2 * 16 * ROWB);
            #pragma unroll
            for (int mi = 0; mi < 2; mi++)
                #pragma unroll
                for (int j2 = 0; j2 < 4; j2++) {
                    mma16816(acc[mi][2*j2],   aH[mi], &bF[j2][0]);
                    mma16816(acc[mi][2*j2+1], aH[mi], &bF[j2][2]);
                }
        }

        if (more) {  // convert + store prefetch into the other buffer
            char* nb = stg + (cur ^ 1) * STAGE;
            uint32_t h[8], l[8];
            split_pack(pa[0].x,pa[0].y,h[0],l[0]); split_pack(pa[0].z,pa[0].w,h[1],l[1]);
            split_pack(pa[1].x,pa[1].y,h[2],l[2]); split_pack(pa[1].z,pa[1].w,h[3],l[3]);
            split_pack(pa[2].x,pa[2].y,h[4],l[4]); split_pack(pa[2].z,pa[2].w,h[5],l[5]);
            split_pack(pa[3].x,pa[3].y,h[6],l[6]); split_pack(pa[3].z,pa[3].w,h[7],l[7]);
            char* pa0 = nb + arow * ROWB + akh * 32;
            *(uint4*)pa0           = make_uint4(h[0],h[1],h[2],h[3]);
            *(uint4*)(pa0 + 16)    = make_uint4(h[4],h[5],h[6],h[7]);
            *(uint4*)(pa0 + PLANE) = make_uint4(l[0],l[1],l[2],l[3]);
            *(uint4*)(pa0 + PLANE + 16) = make_uint4(l[4],l[5],l[6],l[7]);
            split_pack(pb[0],pb[1],h[0],l[0]);  split_pack(pb[2],pb[3],h[1],l[1]);
            split_pack(pb[4],pb[5],h[2],l[2]);  split_pack(pb[6],pb[7],h[3],l[3]);
            split_pack(pb[8],pb[9],h[4],l[4]);  split_pack(pb[10],pb[11],h[5],l[5]);
            split_pack(pb[12],pb[13],h[6],l[6]);split_pack(pb[14],pb[15],h[7],l[7]);
            char* pb0 = nb + 20480 + bn * ROWB + bkh * 32;
            *(uint4*)pb0           = make_uint4(h[0],h[1],h[2],h[3]);
            *(uint4*)(pb0 + 16)    = make_uint4(h[4],h[5],h[6],h[7]);
            *(uint4*)(pb0 + PLANE) = make_uint4(l[0],l[1],l[2],l[3]);
            *(uint4*)(pb0 + PLANE + 16) = make_uint4(l[4],l[5],l[6],l[7]);
        }
        __syncthreads();
    }

    // ---------------------------- epilogue ---------------------------------
    // thread cols: n0 + wn*64 + nj*8 + (lane&3)*2 ; rows: m0 + wm*32 + mi*16 + lane/4 + rr*8
    float b2x[8], b2y[8];
    int   hh[8], dd0[8];
    #pragma unroll
    for (int nj = 0; nj < 8; nj++) {
        const int col = n0 + wn * 64 + nj * 8 + (lane & 3) * 2;
        b2x[nj] = __ldg(&bias[col]);
        b2y[nj] = __ldg(&bias[col + 1]);
        if (IS_QKV) {
            const int h = col / 384, rem = col - h * 384;
            hh[nj] = h * 3 + (rem >> 7);     // encode (head, comp)
            dd0[nj] = rem & 127;
        }
    }
    #pragma unroll
    for (int mi = 0; mi < 2; mi++) {
        #pragma unroll
        for (int rr = 0; rr < 2; rr++) {
            const int row = m0 + wm * 32 + mi * 16 + (lane >> 2) + rr * 8;
            if (IS_QKV) {
                const int bbat = row >> 11, ss = row & 2047;
                #pragma unroll
                for (int nj = 0; nj < 8; nj++) {
                    const int h = hh[nj] / 3, comp = hh[nj] - h * 3;
                    float* dst = ((comp == 0) ? g_q : (comp == 1) ? g_k : g_v)
                               + ((size_t)(bbat * NH + h) * SEQ + ss) * HD + dd0[nj];
                    *(float2*)dst = make_float2(acc[mi][nj][rr*2] + b2x[nj],
                                                acc[mi][nj][rr*2+1] + b2y[nj]);
                }
            } else {
                const size_t o = (size_t)row * HID + n0 + wn * 64 + (lane & 3) * 2;
                #pragma unroll
                for (int nj = 0; nj < 8; nj++) {
                    float2 rv = *(const float2*)(resid + o + nj * 8);
                    *(float2*)(out + o + nj * 8) =
                        make_float2(acc[mi][nj][rr*2] + b2x[nj] + rv.x,
                                    acc[mi][nj][rr*2+1] + b2y[nj] + rv.y);
                }
            }
        }
    }
}

// ======================= flash attention (fp32 SIMT) =======================
#define ATT_SMEM ((128*129*2 + 128*128) * 4)

__global__ void __launch_bounds__(256, 1) attn_kernel(const float* __restrict__ alibi)
{
    extern __shared__ float sm[];
    float* Qs = sm;
    float* Ks = sm + 128 * 129;
    float* Vs = sm + 2 * 128 * 129;

    const int tid = threadIdx.x;
    const int ty = tid >> 4, tx = tid & 15;
    const int qt = blockIdx.x, bh = blockIdx.y;
    const int q0 = qt * 128;

    const float* qptr  = g_q + ((size_t)bh * SEQ + q0) * HD;
    const float* kbase = g_k + (size_t)bh * SEQ * HD;
    const float* vbase = g_v + (size_t)bh * SEQ * HD;
    const float* albase = alibi + (size_t)bh * SEQ;

    for (int idx = tid; idx < 128 * 32; idx += 256) {
        const int r = idx >> 5, c = (idx & 31) * 4;
        float4 v = *(const float4*)(qptr + (size_t)r * HD + c);
        Qs[r*129+c+0] = v.x; Qs[r*129+c+1] = v.y; Qs[r*129+c+2] = v.z; Qs[r*129+c+3] = v.w;
    }

    float acc_o[8][8], mrow[8], lrow[8];
    #pragma unroll
    for (int i = 0; i < 8; i++) {
        mrow[i] = -1e30f; lrow[i] = 0.f;
        #pragma unroll
        for (int j = 0; j < 8; j++) acc_o[i][j] = 0.f;
    }
    const float inv_norm = 0.088388347648318447f;

    for (int kt = 0; kt <= qt; kt++) {
        const int k0 = kt * 128;
        __syncthreads();
        for (int idx = tid; idx < 128 * 32; idx += 256) {
            const int r = idx >> 5, c = (idx & 31) * 4;
            float4 kv = *(const float4*)(kbase + (size_t)(k0 + r) * HD + c);
            Ks[r*129+c+0] = kv.x; Ks[r*129+c+1] = kv.y; Ks[r*129+c+2] = kv.z; Ks[r*129+c+3] = kv.w;
            float4 vv = *(const float4*)(vbase + (size_t)(k0 + r) * HD + c);
            *(float4*)&Vs[r * 128 + c] = vv;
        }
        __syncthreads();

        float s[8][8];
        #pragma unroll
        for (int i = 0; i < 8; i++)
            #pragma unroll
            for (int j = 0; j < 8; j++) s[i][j] = 0.f;
        for (int d = 0; d < 128; d++) {
            float a[8], b[8];
            #pragma unroll
            for (int i = 0; i < 8; i++) a[i] = Qs[(ty + 16*i)*129 + d];
            #pragma unroll
            for (int j = 0; j < 8; j++) b[j] = Ks[(tx + 16*j)*129 + d];
            #pragma unroll
            for (int i = 0; i < 8; i++)
                #pragma unroll
                for (int j = 0; j < 8; j++)
                    s[i][j] = fmaf(a[i], b[j], s[i][j]);
        }

        float al[8];
        #pragma unroll
        for (int j = 0; j < 8; j++) al[j] = __ldg(albase + k0 + tx + 16*j);

        const bool diag = (kt == qt);
        #pragma unroll
        for (int i = 0; i < 8; i++) {
            const int qg = q0 + ty + 16*i;
            float mx = -1e30f;
            #pragma unroll
            for (int j = 0; j < 8; j++) {
                float v = s[i][j] * inv_norm + al[j];
                if (diag && (k0 + tx + 16*j) > qg) v = -1e30f;
                s[i][j] = v;
                mx = fmaxf(mx, v);
            }
            mx = fmaxf(mx, __shfl_xor_sync(0xffffffffu, mx, 1));
            mx = fmaxf(mx, __shfl_xor_sync(0xffffffffu, mx, 2));
            mx = fmaxf(mx, __shfl_xor_sync(0xffffffffu, mx, 4));
            mx = fmaxf(mx, __shfl_xor_sync(0xffffffffu, mx, 8));
            const float mnew = fmaxf(mrow[i], mx);
            const float corr = __expf(mrow[i] - mnew);
            float ls = 0.f;
            #pragma unroll
            for (int j = 0; j < 8; j++) {
                float p = __expf(s[i][j] - mnew);
                s[i][j] = p; ls += p;
            }
            ls += __shfl_xor_sync(0xffffffffu, ls, 1);
            ls += __shfl_xor_sync(0xffffffffu, ls, 2);
            ls += __shfl_xor_sync(0xffffffffu, ls, 4);
            ls += __shfl_xor_sync(0xffffffffu, ls, 8);
            lrow[i] = lrow[i] * corr + ls;
            mrow[i] = mnew;
            #pragma unroll
            for (int j = 0; j < 8; j++) acc_o[i][j] *= corr;
        }

        __syncthreads();
        #pragma unroll
        for (int i = 0; i < 8; i++)
            #pragma unroll
            for (int j = 0; j < 8; j++)
                Ks[(ty + 16*i)*129 + (tx + 16*j)] = s[i][j];
        __syncthreads();

        for (int kk = 0; kk < 128; kk++) {
            float a[8], b[8];
            #pragma unroll
            for (int i = 0; i < 8; i++) a[i] = Ks[(ty + 16*i)*129 + kk];
            #pragma unroll
            for (int j = 0; j < 8; j++) b[j] = Vs[kk*128 + tx + 16*j];
            #pragma unroll
            for (int i = 0; i < 8; i++)
                #pragma unroll
                for (int j = 0; j < 8; j++)
                    acc_o[i][j] = fmaf(a[i], b[j], acc_o[i][j]);
        }
    }

    const int b = bh >> 5, h = bh & 31;
    #pragma unroll
    for (int i = 0; i < 8; i++) {
        const float invl = 1.f / lrow[i];
        const int srow = q0 + ty + 16*i;
        float* op = g_ctx + ((size_t)(b * SEQ + srow)) * HID + h * HD;
        #pragma unroll
        for (int j = 0; j < 8; j++)
            op[tx + 16*j] = acc_o[i][j] * invl;
    }
}

// =============================== launch ====================================
extern "C" void kernel_launch(void* const* d_in, const int* in_sizes, int n_in,
                              void* d_out, int out_size)
{
    const float* hs    = (const float*)d_in[0];
    const float* resid = (const float*)d_in[1];
    const float* alibi = (const float*)d_in[2];
    const float* Wqkv  = (const float*)d_in[4];
    const float* bqkv  = (const float*)d_in[5];
    const float* Wd    = (const float*)d_in[6];
    const float* bd    = (const float*)d_in[7];
    float* out = (float*)d_out;

    cudaFuncSetAttribute(gemm_mma_kernel<true>,
                         cudaFuncAttributeMaxDynamicSharedMemorySize, GEMM_SMEM);
    cudaFuncSetAttribute(gemm_mma_kernel<false>,
                         cudaFuncAttributeMaxDynamicSharedMemorySize, GEMM_SMEM);
    cudaFuncSetAttribute(attn_kernel,
                         cudaFuncAttributeMaxDynamicSharedMemorySize, ATT_SMEM);

    gemm_mma_kernel<true><<<dim3(NQKV/128, MROWS/128), 256, GEMM_SMEM>>>(hs, Wqkv, bqkv, nullptr, nullptr);
    attn_kernel<<<dim3(SEQ/128, BATCH*NH), 256, ATT_SMEM>>>(alibi);
    gemm_mma_kernel<false><<<dim3(HID/128, MROWS/128), 256, GEMM_SMEM>>>(nullptr, Wd, bd, resid, out);
}

// round 5
// speedup vs baseline: 2.4423x; 1.2142x over previous
#include <cuda_runtime.h>
#include <cuda_bf16.h>
#include <stdint.h>

#define HID   4096
#define SEQ   2048
#define BATCH 2
#define NH    32
#define HD    128
#define MROWS (BATCH*SEQ)
#define NQKV  (3*HID)

__device__ float g_q[(size_t)BATCH*NH*SEQ*HD];
__device__ float g_k[(size_t)BATCH*NH*SEQ*HD];
__device__ float g_v[(size_t)BATCH*NH*SEQ*HD];
__device__ float g_ctx[(size_t)BATCH*SEQ*HID];

// ============================ helpers ======================================
__device__ __forceinline__ uint32_t smem_u32(const void* p) {
    uint32_t a;
    asm("{ .reg .u64 t; cvta.to.shared.u64 t, %1; cvt.u32.u64 %0, t; }" : "=r"(a) : "l"(p));
    return a;
}
__device__ __forceinline__ void ldsm4(uint32_t* r, uint32_t addr) {
    asm volatile("ldmatrix.sync.aligned.m8n8.x4.shared.b16 {%0,%1,%2,%3}, [%4];"
                 : "=r"(r[0]), "=r"(r[1]), "=r"(r[2]), "=r"(r[3]) : "r"(addr));
}
__device__ __forceinline__ void mma16816(float* d, const uint32_t* a, const uint32_t* b) {
    asm volatile("mma.sync.aligned.m16n8k16.row.col.f32.bf16.bf16.f32 "
                 "{%0,%1,%2,%3}, {%4,%5,%6,%7}, {%8,%9}, {%0,%1,%2,%3};"
                 : "+f"(d[0]), "+f"(d[1]), "+f"(d[2]), "+f"(d[3])
                 : "r"(a[0]), "r"(a[1]), "r"(a[2]), "r"(a[3]), "r"(b[0]), "r"(b[1]));
}
__device__ __forceinline__ void split_pack(float a, float b, uint32_t& h, uint32_t& l) {
    __nv_bfloat162 hb = __floats2bfloat162_rn(a, b);
    float la = a - __bfloat162float(hb.x);
    float lb = b - __bfloat162float(hb.y);
    __nv_bfloat162 lo2 = __floats2bfloat162_rn(la, lb);
    h = *(uint32_t*)&hb; l = *(uint32_t*)&lo2;
}

// ====================== GEMM (unchanged from R4, passing) ==================
#define ROWB   80
#define PLANE  10240
#define STAGE  40960
#define GEMM_SMEM (2 * STAGE)

template <bool IS_QKV>
__global__ void __launch_bounds__(256, 1)
gemm_mma_kernel(const float* __restrict__ Ain, const float* __restrict__ W,
                const float* __restrict__ bias, const float* __restrict__ resid,
                float* __restrict__ out)
{
    constexpr int N  = IS_QKV ? NQKV : HID;
    constexpr int NC = HID / 32;
    extern __shared__ __align__(16) char stg[];
    const uint32_t stg_u = smem_u32(stg);

    const float* A = IS_QKV ? Ain : (const float*)g_ctx;
    const int tid  = threadIdx.x;
    const int wid  = tid >> 5, lane = tid & 31;
    const int wm   = wid >> 1, wn = wid & 1;
    const int m0   = blockIdx.y * 128, n0 = blockIdx.x * 128;

    const int arow = tid >> 1, akh = tid & 1;
    const int bn   = tid & 127, bkh = tid >> 7;
    const float* apg = A + (size_t)(m0 + arow) * HID + akh * 16;
    const float* wpg = W + (size_t)(bkh * 16) * N + n0 + bn;

    float acc[2][8][4];
    #pragma unroll
    for (int mi = 0; mi < 2; mi++)
        #pragma unroll
        for (int nj = 0; nj < 8; nj++)
            #pragma unroll
            for (int r = 0; r < 4; r++) acc[mi][nj][r] = 0.f;

    float4 pa[4];
    float  pb[16];

    const uint32_t a_base = stg_u + (uint32_t)(wm * 32 + (lane & 15)) * ROWB + ((lane >> 4) << 4);
    const uint32_t b_base = stg_u + 20480u
                          + (uint32_t)(wn * 64 + (lane & 7) + ((lane >> 4) << 3)) * ROWB
                          + (((lane >> 3) & 1) << 4);

    {
        const float* ap = apg;
        float4 q0 = *(const float4*)ap, q1 = *(const float4*)(ap + 4);
        float4 q2 = *(const float4*)(ap + 8), q3 = *(const float4*)(ap + 12);
        uint32_t h[8], l[8];
        split_pack(q0.x,q0.y,h[0],l[0]); split_pack(q0.z,q0.w,h[1],l[1]);
        split_pack(q1.x,q1.y,h[2],l[2]); split_pack(q1.z,q1.w,h[3],l[3]);
        split_pack(q2.x,q2.y,h[4],l[4]); split_pack(q2.z,q2.w,h[5],l[5]);
        split_pack(q3.x,q3.y,h[6],l[6]); split_pack(q3.z,q3.w,h[7],l[7]);
        char* pa0 = stg + arow * ROWB + akh * 32;
        *(uint4*)pa0           = make_uint4(h[0],h[1],h[2],h[3]);
        *(uint4*)(pa0 + 16)    = make_uint4(h[4],h[5],h[6],h[7]);
        *(uint4*)(pa0 + PLANE) = make_uint4(l[0],l[1],l[2],l[3]);
        *(uint4*)(pa0 + PLANE + 16) = make_uint4(l[4],l[5],l[6],l[7]);
        float f[16];
        #pragma unroll
        for (int j = 0; j < 16; j++) f[j] = __ldg(wpg + (size_t)j * N);
        split_pack(f[0],f[1],h[0],l[0]);  split_pack(f[2],f[3],h[1],l[1]);
        split_pack(f[4],f[5],h[2],l[2]);  split_pack(f[6],f[7],h[3],l[3]);
        split_pack(f[8],f[9],h[4],l[4]);  split_pack(f[10],f[11],h[5],l[5]);
        split_pack(f[12],f[13],h[6],l[6]);split_pack(f[14],f[15],h[7],l[7]);
        char* pb0 = stg + 20480 + bn * ROWB + bkh * 32;
        *(uint4*)pb0           = make_uint4(h[0],h[1],h[2],h[3]);
        *(uint4*)(pb0 + 16)    = make_uint4(h[4],h[5],h[6],h[7]);
        *(uint4*)(pb0 + PLANE) = make_uint4(l[0],l[1],l[2],l[3]);
        *(uint4*)(pb0 + PLANE + 16) = make_uint4(l[4],l[5],l[6],l[7]);
    }
    __syncthreads();

    for (int c = 0; c < NC; c++) {
        const int cur = c & 1;
        const bool more = (c + 1 < NC);
        if (more) {
            const int k0 = (c + 1) * 32;
            const float* ap = apg + k0;
            pa[0] = *(const float4*)ap;       pa[1] = *(const float4*)(ap + 4);
            pa[2] = *(const float4*)(ap + 8); pa[3] = *(const float4*)(ap + 12);
            const float* wp = wpg + (size_t)k0 * N;
            #pragma unroll
            for (int j = 0; j < 16; j++) pb[j] = __ldg(wp + (size_t)j * N);
        }

        const uint32_t ab = a_base + cur * STAGE;
        const uint32_t bb = b_base + cur * STAGE;
        #pragma unroll
        for (int kk = 0; kk < 2; kk++) {
            uint32_t aH[2][4], aL[2][4], bF[4][4];
            ldsm4(aH[0], ab + kk * 32);
            ldsm4(aH[1], ab + kk * 32 + 16 * ROWB);
            ldsm4(aL[0], ab + PLANE + kk * 32);
            ldsm4(aL[1], ab + PLANE + kk * 32 + 16 * ROWB);
            #pragma unroll
            for (int j2 = 0; j2 < 4; j2++) ldsm4(bF[j2], bb + kk * 32 + j2 * 16 * ROWB);
            #pragma unroll
            for (int mi = 0; mi < 2; mi++)
                #pragma unroll
                for (int j2 = 0; j2 < 4; j2++) {
                    mma16816(acc[mi][2*j2],   aH[mi], &bF[j2][0]);
                    mma16816(acc[mi][2*j2+1], aH[mi], &bF[j2][2]);
                }
            #pragma unroll
            for (int mi = 0; mi < 2; mi++)
                #pragma unroll
                for (int j2 = 0; j2 < 4; j2++) {
                    mma16816(acc[mi][2*j2],   aL[mi], &bF[j2][0]);
                    mma16816(acc[mi][2*j2+1], aL[mi], &bF[j2][2]);
                }
            #pragma unroll
            for (int j2 = 0; j2 < 4; j2++) ldsm4(bF[j2], bb + PLANE + kk * 32 + j2 * 16 * ROWB);
            #pragma unroll
            for (int mi = 0; mi < 2; mi++)
                #pragma unroll
                for (int j2 = 0; j2 < 4; j2++) {
                    mma16816(acc[mi][2*j2],   aH[mi], &bF[j2][0]);
                    mma16816(acc[mi][2*j2+1], aH[mi], &bF[j2][2]);
                }
        }

        if (more) {
            char* nb = stg + (cur ^ 1) * STAGE;
            uint32_t h[8], l[8];
            split_pack(pa[0].x,pa[0].y,h[0],l[0]); split_pack(pa[0].z,pa[0].w,h[1],l[1]);
            split_pack(pa[1].x,pa[1].y,h[2],l[2]); split_pack(pa[1].z,pa[1].w,h[3],l[3]);
            split_pack(pa[2].x,pa[2].y,h[4],l[4]); split_pack(pa[2].z,pa[2].w,h[5],l[5]);
            split_pack(pa[3].x,pa[3].y,h[6],l[6]); split_pack(pa[3].z,pa[3].w,h[7],l[7]);
            char* pa0 = nb + arow * ROWB + akh * 32;
            *(uint4*)pa0           = make_uint4(h[0],h[1],h[2],h[3]);
            *(uint4*)(pa0 + 16)    = make_uint4(h[4],h[5],h[6],h[7]);
            *(uint4*)(pa0 + PLANE) = make_uint4(l[0],l[1],l[2],l[3]);
            *(uint4*)(pa0 + PLANE + 16) = make_uint4(l[4],l[5],l[6],l[7]);
            split_pack(pb[0],pb[1],h[0],l[0]);  split_pack(pb[2],pb[3],h[1],l[1]);
            split_pack(pb[4],pb[5],h[2],l[2]);  split_pack(pb[6],pb[7],h[3],l[3]);
            split_pack(pb[8],pb[9],h[4],l[4]);  split_pack(pb[10],pb[11],h[5],l[5]);
            split_pack(pb[12],pb[13],h[6],l[6]);split_pack(pb[14],pb[15],h[7],l[7]);
            char* pb0 = nb + 20480 + bn * ROWB + bkh * 32;
            *(uint4*)pb0           = make_uint4(h[0],h[1],h[2],h[3]);
            *(uint4*)(pb0 + 16)    = make_uint4(h[4],h[5],h[6],h[7]);
            *(uint4*)(pb0 + PLANE) = make_uint4(l[0],l[1],l[2],l[3]);
            *(uint4*)(pb0 + PLANE + 16) = make_uint4(l[4],l[5],l[6],l[7]);
        }
        __syncthreads();
    }

    float b2x[8], b2y[8];
    int   hh[8], dd0[8];
    #pragma unroll
    for (int nj = 0; nj < 8; nj++) {
        const int col = n0 + wn * 64 + nj * 8 + (lane & 3) * 2;
        b2x[nj] = __ldg(&bias[col]);
        b2y[nj] = __ldg(&bias[col + 1]);
        if (IS_QKV) {
            const int h = col / 384, rem = col - h * 384;
            hh[nj] = h * 3 + (rem >> 7);
            dd0[nj] = rem & 127;
        }
    }
    #pragma unroll
    for (int mi = 0; mi < 2; mi++) {
        #pragma unroll
        for (int rr = 0; rr < 2; rr++) {
            const int row = m0 + wm * 32 + mi * 16 + (lane >> 2) + rr * 8;
            if (IS_QKV) {
                const int bbat = row >> 11, ss = row & 2047;
                #pragma unroll
                for (int nj = 0; nj < 8; nj++) {
                    const int h = hh[nj] / 3, comp = hh[nj] - h * 3;
                    float* dst = ((comp == 0) ? g_q : (comp == 1) ? g_k : g_v)
                               + ((size_t)(bbat * NH + h) * SEQ + ss) * HD + dd0[nj];
                    *(float2*)dst = make_float2(acc[mi][nj][rr*2] + b2x[nj],
                                                acc[mi][nj][rr*2+1] + b2y[nj]);
                }
            } else {
                const size_t o = (size_t)row * HID + n0 + wn * 64 + (lane & 3) * 2;
                #pragma unroll
                for (int nj = 0; nj < 8; nj++) {
                    float2 rv = *(const float2*)(resid + o + nj * 8);
                    *(float2*)(out + o + nj * 8) =
                        make_float2(acc[mi][nj][rr*2] + b2x[nj] + rv.x,
                                    acc[mi][nj][rr*2+1] + b2y[nj] + rv.y);
                }
            }
        }
    }
}

// ==================== tensor-core flash attention ==========================
// smem planes (row stride 272B, 128 rows each): Qh Ql | Kh Kl (reused as P) | Vh Vl
#define STR  272
#define PLN  (128*STR)          /* 34816 */
#define ATT_SMEM (6*PLN)        /* 208896 */

// load 128x128 fp32 tile (row stride HD) -> hi/lo bf16 planes, optional scale
__device__ __forceinline__ void att_load_tile(const float* __restrict__ src,
                                              char* hi, char* lo, float scale, int tid)
{
    const int r = tid >> 1, ch = (tid & 1) * 64;
    const float* p = src + (size_t)r * HD + ch;
    char* ph = hi + r * STR + ch * 2;
    char* pl = lo + r * STR + ch * 2;
    #pragma unroll
    for (int i = 0; i < 8; i++) {
        float4 v0 = *(const float4*)(p + i * 8);
        float4 v1 = *(const float4*)(p + i * 8 + 4);
        uint32_t h0,h1,h2,h3,l0,l1,l2,l3;
        split_pack(v0.x*scale, v0.y*scale, h0, l0);
        split_pack(v0.z*scale, v0.w*scale, h1, l1);
        split_pack(v1.x*scale, v1.y*scale, h2, l2);
        split_pack(v1.z*scale, v1.w*scale, h3, l3);
        *(uint4*)(ph + i * 16) = make_uint4(h0,h1,h2,h3);
        *(uint4*)(pl + i * 16) = make_uint4(l0,l1,l2,l3);
    }
}

// load V 128x128 fp32 and TRANSPOSE into [d][key] hi/lo planes
__device__ __forceinline__ void att_load_vtile(const float* __restrict__ src,
                                               char* hi, char* lo, int tid)
{
    const int kp = tid & 63;        // keys 2kp, 2kp+1
    const int dg = tid >> 6;        // d-group of 32
    const float* p0 = src + (size_t)(2 * kp) * HD + dg * 32;
    const float* p1 = p0 + HD;
    #pragma unroll
    for (int i = 0; i < 8; i++) {
        float4 a = *(const float4*)(p0 + i * 4);
        float4 b = *(const float4*)(p1 + i * 4);
        const int d = dg * 32 + i * 4;
        uint32_t h, l;
        split_pack(a.x, b.x, h, l);
        *(uint32_t*)(hi + (d+0) * STR + kp * 4) = h;
        *(uint32_t*)(lo + (d+0) * STR + kp * 4) = l;
        split_pack(a.y, b.y, h, l);
        *(uint32_t*)(hi + (d+1) * STR + kp * 4) = h;
        *(uint32_t*)(lo + (d+1) * STR + kp * 4) = l;
        split_pack(a.z, b.z, h, l);
        *(uint32_t*)(hi + (d+2) * STR + kp * 4) = h;
        *(uint32_t*)(lo + (d+2) * STR + kp * 4) = l;
        split_pack(a.w, b.w, h, l);
        *(uint32_t*)(hi + (d+3) * STR + kp * 4) = h;
        *(uint32_t*)(lo + (d+3) * STR + kp * 4) = l;
    }
}

__global__ void __launch_bounds__(256, 1) attn_mma_kernel(const float* __restrict__ alibi)
{
    extern __shared__ __align__(16) char sm[];
    char* Qh = sm;           char* Ql = sm + PLN;
    char* Kh = sm + 2*PLN;   char* Kl = sm + 3*PLN;   // later holds P hi/lo
    char* Vh = sm + 4*PLN;   char* Vl = sm + 5*PLN;
    __shared__ float red_mx[2][128];
    __shared__ float red_sm[2][128];

    const int tid = threadIdx.x;
    const int wid = tid >> 5, lane = tid & 31;
    const int wm = wid >> 1, wn = wid & 1;
    const int qt = gridDim.x - 1 - blockIdx.x;     // heavy tiles first
    const int bh = blockIdx.y;
    const int q0 = qt * 128;
    const float inv_norm = 0.088388347648318447f;  // 1/sqrt(128)

    // Q (scaled) -> smem hi/lo once
    att_load_tile(g_q + ((size_t)bh * SEQ + q0) * HD, Qh, Ql, inv_norm, tid);

    // ldmatrix fragment bases
    const uint32_t a_off = (uint32_t)(wm * 32 + (lane & 15)) * STR + ((lane >> 4) << 4);
    const uint32_t b_off = (uint32_t)(wn * 64 + (lane & 7) + ((lane >> 4) << 3)) * STR
                         + (((lane >> 3) & 1) << 4);
    const uint32_t qh_b = smem_u32(Qh) + a_off, ql_b = smem_u32(Ql) + a_off;
    const uint32_t kh_b = smem_u32(Kh) + b_off, kl_b = smem_u32(Kl) + b_off;
    const uint32_t vh_b = smem_u32(Vh) + b_off, vl_b = smem_u32(Vl) + b_off;
    const uint32_t ph_b = smem_u32(Kh) + a_off, pl_b = smem_u32(Kl) + a_off;

    float o[2][8][4];
    float m_[2][2], l_[2][2], corr[2][2];
    #pragma unroll
    for (int mi = 0; mi < 2; mi++)
        #pragma unroll
        for (int rr = 0; rr < 2; rr++) { m_[mi][rr] = -1e30f; l_[mi][rr] = 0.f; }
    #pragma unroll
    for (int mi = 0; mi < 2; mi++)
        #pragma unroll
        for (int nj = 0; nj < 8; nj++)
            #pragma unroll
            for (int r = 0; r < 4; r++) o[mi][nj][r] = 0.f;

    const float* albase = alibi + (size_t)bh * SEQ;
    const int rbase = wm * 32 + (lane >> 2);       // local row base

    for (int kt = 0; kt <= qt; kt++) {
        const int k0 = kt * 128;
        __syncthreads();   // prev PV done reading K(P)/V; Q visible on iter 0
        att_load_tile(g_k + ((size_t)bh * SEQ + k0) * HD, Kh, Kl, 1.f, tid);
        att_load_vtile(g_v + ((size_t)bh * SEQ + k0) * HD, Vh, Vl, tid);
        __syncthreads();

        // ---- S = Q K^T (bf16x3) ----
        float s[2][8][4];
        #pragma unroll
        for (int mi = 0; mi < 2; mi++)
            #pragma unroll
            for (int nj = 0; nj < 8; nj++)
                #pragma unroll
                for (int r = 0; r < 4; r++) s[mi][nj][r] = 0.f;
        #pragma unroll
        for (int kk = 0; kk < 8; kk++) {
            uint32_t aH[2][4], aL[2][4], bF[4][4];
            ldsm4(aH[0], qh_b + kk * 32);
            ldsm4(aH[1], qh_b + kk * 32 + 16 * STR);
            ldsm4(aL[0], ql_b + kk * 32);
            ldsm4(aL[1], ql_b + kk * 32 + 16 * STR);
            #pragma unroll
            for (int j2 = 0; j2 < 4; j2++) ldsm4(bF[j2], kh_b + kk * 32 + j2 * 16 * STR);
            #pragma unroll
            for (int mi = 0; mi < 2; mi++)
                #pragma unroll
                for (int j2 = 0; j2 < 4; j2++) {
                    mma16816(s[mi][2*j2],   aH[mi], &bF[j2][0]);
                    mma16816(s[mi][2*j2+1], aH[mi], &bF[j2][2]);
                }
            #pragma unroll
            for (int mi = 0; mi < 2; mi++)
                #pragma unroll
                for (int j2 = 0; j2 < 4; j2++) {
                    mma16816(s[mi][2*j2],   aL[mi], &bF[j2][0]);
                    mma16816(s[mi][2*j2+1], aL[mi], &bF[j2][2]);
                }
            #pragma unroll
            for (int j2 = 0; j2 < 4; j2++) ldsm4(bF[j2], kl_b + kk * 32 + j2 * 16 * STR);
            #pragma unroll
            for (int mi = 0; mi < 2; mi++)
                #pragma unroll
                for (int j2 = 0; j2 < 4; j2++) {
                    mma16816(s[mi][2*j2],   aH[mi], &bF[j2][0]);
                    mma16816(s[mi][2*j2+1], aH[mi], &bF[j2][2]);
                }
        }

        // ---- alibi + causal mask + partial row max ----
        float al[8][2];
        #pragma unroll
        for (int nj = 0; nj < 8; nj++) {
            const int col = k0 + wn * 64 + nj * 8 + (lane & 3) * 2;
            al[nj][0] = __ldg(albase + col);
            al[nj][1] = __ldg(albase + col + 1);
        }
        const bool diag = (kt == qt);
        #pragma unroll
        for (int mi = 0; mi < 2; mi++) {
            #pragma unroll
            for (int rr = 0; rr < 2; rr++) {
                const int rloc = rbase + mi * 16 + rr * 8;
                const int rowg = q0 + rloc;
                float mx = -1e30f;
                #pragma unroll
                for (int nj = 0; nj < 8; nj++) {
                    #pragma unroll
                    for (int e = 0; e < 2; e++) {
                        float v = s[mi][nj][rr*2+e] + al[nj][e];
                        if (diag && (k0 + wn*64 + nj*8 + (lane&3)*2 + e) > rowg) v = -1e30f;
                        s[mi][nj][rr*2+e] = v;
                        mx = fmaxf(mx, v);
                    }
                }
                mx = fmaxf(mx, __shfl_xor_sync(0xffffffffu, mx, 1));
                mx = fmaxf(mx, __shfl_xor_sync(0xffffffffu, mx, 2));
                if ((lane & 3) == 0) red_mx[wn][rloc] = mx;
            }
        }
        __syncthreads();

        // ---- softmax: combine max, exp, partial sums, scale O ----
        #pragma unroll
        for (int mi = 0; mi < 2; mi++) {
            #pragma unroll
            for (int rr = 0; rr < 2; rr++) {
                const int rloc = rbase + mi * 16 + rr * 8;
                const float mx = fmaxf(red_mx[0][rloc], red_mx[1][rloc]);
                const float mnew = fmaxf(m_[mi][rr], mx);
                const float cr = __expf(m_[mi][rr] - mnew);
                corr[mi][rr] = cr;
                m_[mi][rr] = mnew;
                float ls = 0.f;
                #pragma unroll
                for (int nj = 0; nj < 8; nj++) {
                    #pragma unroll
                    for (int e = 0; e < 2; e++) {
                        float p = __expf(s[mi][nj][rr*2+e] - mnew);
                        s[mi][nj][rr*2+e] = p;
                        ls += p;
                    }
                }
                ls += __shfl_xor_sync(0xffffffffu, ls, 1);
                ls += __shfl_xor_sync(0xffffffffu, ls, 2);
                if ((lane & 3) == 0) red_sm[wn][rloc] = ls;
                #pragma unroll
                for (int nj = 0; nj < 8; nj++) {
                    o[mi][nj][rr*2]   *= cr;
                    o[mi][nj][rr*2+1] *= cr;
                }
            }
        }
        __syncthreads();
        #pragma unroll
        for (int mi = 0; mi < 2; mi++)
            #pragma unroll
            for (int rr = 0; rr < 2; rr++) {
                const int rloc = rbase + mi * 16 + rr * 8;
                l_[mi][rr] = l_[mi][rr] * corr[mi][rr] + red_sm[0][rloc] + red_sm[1][rloc];
            }

        // ---- write P (hi/lo) into K buffers (S-mma long done) ----
        #pragma unroll
        for (int mi = 0; mi < 2; mi++) {
            #pragma unroll
            for (int rr = 0; rr < 2; rr++) {
                const uint32_t roff = (uint32_t)(rbase + mi * 16 + rr * 8) * STR
                                    + (wn * 64 + (lane & 3) * 2) * 2;
                #pragma unroll
                for (int nj = 0; nj < 8; nj++) {
                    uint32_t h, l;
                    split_pack(s[mi][nj][rr*2], s[mi][nj][rr*2+1], h, l);
                    *(uint32_t*)(Kh + roff + nj * 16) = h;
                    *(uint32_t*)(Kl + roff + nj * 16) = l;
                }
            }
        }
        __syncthreads();

        // ---- O += P V (bf16x3) ----
        #pragma unroll
        for (int kk = 0; kk < 8; kk++) {
            uint32_t aH[2][4], aL[2][4], bF[4][4];
            ldsm4(aH[0], ph_b + kk * 32);
            ldsm4(aH[1], ph_b + kk * 32 + 16 * STR);
            ldsm4(aL[0], pl_b + kk * 32);
            ldsm4(aL[1], pl_b + kk * 32 + 16 * STR);
            #pragma unroll
            for (int j2 = 0; j2 < 4; j2++) ldsm4(bF[j2], vh_b + kk * 32 + j2 * 16 * STR);
            #pragma unroll
            for (int mi = 0; mi < 2; mi++)
                #pragma unroll
                for (int j2 = 0; j2 < 4; j2++) {
                    mma16816(o[mi][2*j2],   aH[mi], &bF[j2][0]);
                    mma16816(o[mi][2*j2+1], aH[mi], &bF[j2][2]);
                }
            #pragma unroll
            for (int mi = 0; mi < 2; mi++)
                #pragma unroll
                for (int j2 = 0; j2 < 4; j2++) {
                    mma16816(o[mi][2*j2],   aL[mi], &bF[j2][0]);
                    mma16816(o[mi][2*j2+1], aL[mi], &bF[j2][2]);
                }
            #pragma unroll
            for (int j2 = 0; j2 < 4; j2++) ldsm4(bF[j2], vl_b + kk * 32 + j2 * 16 * STR);
            #pragma unroll
            for (int mi = 0; mi < 2; mi++)
                #pragma unroll
                for (int j2 = 0; j2 < 4; j2++) {
                    mma16816(o[mi][2*j2],   aH[mi], &bF[j2][0]);
                    mma16816(o[mi][2*j2+1], aH[mi], &bF[j2][2]);
                }
        }
    }

    // ---- epilogue: O/l -> g_ctx[b, s, h*HD + d] ----
    const int b = bh >> 5, h = bh & 31;
    #pragma unroll
    for (int mi = 0; mi < 2; mi++) {
        #pragma unroll
        for (int rr = 0; rr < 2; rr++) {
            const float invl = 1.f / l_[mi][rr];
            const int srow = q0 + rbase + mi * 16 + rr * 8;
            float* op = g_ctx + ((size_t)(b * SEQ + srow)) * HID + h * HD
                      + wn * 64 + (lane & 3) * 2;
            #pragma unroll
            for (int nj = 0; nj < 8; nj++)
                *(float2*)(op + nj * 8) = make_float2(o[mi][nj][rr*2] * invl,
                                                      o[mi][nj][rr*2+1] * invl);
        }
    }
}

// =============================== launch ====================================
extern "C" void kernel_launch(void* const* d_in, const int* in_sizes, int n_in,
                              void* d_out, int out_size)
{
    const float* hs    = (const float*)d_in[0];
    const float* resid = (const float*)d_in[1];
    const float* alibi = (const float*)d_in[2];
    const float* Wqkv  = (const float*)d_in[4];
    const float* bqkv  = (const float*)d_in[5];
    const float* Wd    = (const float*)d_in[6];
    const float* bd    = (const float*)d_in[7];
    float* out = (float*)d_out;

    cudaFuncSetAttribute(gemm_mma_kernel<true>,
                         cudaFuncAttributeMaxDynamicSharedMemorySize, GEMM_SMEM);
    cudaFuncSetAttribute(gemm_mma_kernel<false>,
                         cudaFuncAttributeMaxDynamicSharedMemorySize, GEMM_SMEM);
    cudaFuncSetAttribute(attn_mma_kernel,
                         cudaFuncAttributeMaxDynamicSharedMemorySize, ATT_SMEM);

    gemm_mma_kernel<true><<<dim3(NQKV/128, MROWS/128), 256, GEMM_SMEM>>>(hs, Wqkv, bqkv, nullptr, nullptr);
    attn_mma_kernel<<<dim3(SEQ/128, BATCH*NH), 256, ATT_SMEM>>>(alibi);
    gemm_mma_kernel<false><<<dim3(HID/128, MROWS/128), 256, GEMM_SMEM>>>(nullptr, Wd, bd, resid, out);
}

// round 6
// speedup vs baseline: 3.3907x; 1.3883x over previous
#include <cuda_runtime.h>
#include <cuda_fp16.h>
#include <stdint.h>

#define HID   4096
#define SEQ   2048
#define BATCH 2
#define NH    32
#define HD    128
#define MROWS (BATCH*SEQ)
#define NQKV  (3*HID)

__device__ float g_q[(size_t)BATCH*NH*SEQ*HD];
__device__ float g_k[(size_t)BATCH*NH*SEQ*HD];
__device__ float g_v[(size_t)BATCH*NH*SEQ*HD];
__device__ float g_ctx[(size_t)BATCH*SEQ*HID];

// ============================ helpers ======================================
__device__ __forceinline__ uint32_t smem_u32(const void* p) {
    uint32_t a;
    asm("{ .reg .u64 t; cvta.to.shared.u64 t, %1; cvt.u32.u64 %0, t; }" : "=r"(a) : "l"(p));
    return a;
}
__device__ __forceinline__ void ldsm4(uint32_t* r, uint32_t addr) {
    asm volatile("ldmatrix.sync.aligned.m8n8.x4.shared.b16 {%0,%1,%2,%3}, [%4];"
                 : "=r"(r[0]), "=r"(r[1]), "=r"(r[2]), "=r"(r[3]) : "r"(addr));
}
__device__ __forceinline__ void mma16816(float* d, const uint32_t* a, const uint32_t* b) {
    asm volatile("mma.sync.aligned.m16n8k16.row.col.f32.f16.f16.f32 "
                 "{%0,%1,%2,%3}, {%4,%5,%6,%7}, {%8,%9}, {%0,%1,%2,%3};"
                 : "+f"(d[0]), "+f"(d[1]), "+f"(d[2]), "+f"(d[3])
                 : "r"(a[0]), "r"(a[1]), "r"(a[2]), "r"(a[3]), "r"(b[0]), "r"(b[1]));
}
// pack two fp32 -> fp16x2 (hi) ; split version also returns exact residual (lo)
__device__ __forceinline__ uint32_t pack_h(float a, float b) {
    __half2 hh = __floats2half2_rn(a, b);
    return *(uint32_t*)&hh;
}
__device__ __forceinline__ void split_pack(float a, float b, uint32_t& h, uint32_t& l) {
    __half2 hh = __floats2half2_rn(a, b);
    float la = a - __half2float(__low2half(hh));
    float lb = b - __half2float(__high2half(hh));
    __half2 ll = __floats2half2_rn(la, lb);
    h = *(uint32_t*)&hh; l = *(uint32_t*)&ll;
}

// ====================== fp16 2-pass GEMM ===================================
// stage: Ah@0 (10240) | Bh@10240 | Bl@20480 ; 80B row stride (32 k * 2B + pad)
#define ROWB   80
#define PLANE  10240
#define STAGE  30720
#define GEMM_SMEM (2 * STAGE)

template <bool IS_QKV>
__global__ void __launch_bounds__(256, 2)
gemm_mma_kernel(const float* __restrict__ Ain, const float* __restrict__ W,
                const float* __restrict__ bias, const float* __restrict__ resid,
                float* __restrict__ out)
{
    constexpr int N  = IS_QKV ? NQKV : HID;
    constexpr int NC = HID / 32;
    extern __shared__ __align__(16) char stg[];
    const uint32_t stg_u = smem_u32(stg);

    const float* A = IS_QKV ? Ain : (const float*)g_ctx;
    const int tid  = threadIdx.x;
    const int wid  = tid >> 5, lane = tid & 31;
    const int wm   = wid >> 1, wn = wid & 1;
    const int m0   = blockIdx.y * 128, n0 = blockIdx.x * 128;

    const int arow = tid >> 1, akh = tid & 1;
    const int bn   = tid & 127, bkh = tid >> 7;
    const float* apg = A + (size_t)(m0 + arow) * HID + akh * 16;
    const float* wpg = W + (size_t)(bkh * 16) * N + n0 + bn;

    float acc[2][8][4];
    #pragma unroll
    for (int mi = 0; mi < 2; mi++)
        #pragma unroll
        for (int nj = 0; nj < 8; nj++)
            #pragma unroll
            for (int r = 0; r < 4; r++) acc[mi][nj][r] = 0.f;

    float4 pa[4];
    float  pb[16];

    const uint32_t a_base = stg_u + (uint32_t)(wm * 32 + (lane & 15)) * ROWB + ((lane >> 4) << 4);
    const uint32_t b_base = stg_u + PLANE
                          + (uint32_t)(wn * 64 + (lane & 7) + ((lane >> 4) << 3)) * ROWB
                          + (((lane >> 3) & 1) << 4);

    // prologue: chunk 0
    {
        const float* ap = apg;
        float4 q0 = *(const float4*)ap, q1 = *(const float4*)(ap + 4);
        float4 q2 = *(const float4*)(ap + 8), q3 = *(const float4*)(ap + 12);
        char* pa0 = stg + arow * ROWB + akh * 32;
        *(uint4*)pa0 = make_uint4(pack_h(q0.x,q0.y), pack_h(q0.z,q0.w),
                                  pack_h(q1.x,q1.y), pack_h(q1.z,q1.w));
        *(uint4*)(pa0 + 16) = make_uint4(pack_h(q2.x,q2.y), pack_h(q2.z,q2.w),
                                         pack_h(q3.x,q3.y), pack_h(q3.z,q3.w));
        float f[16];
        #pragma unroll
        for (int j = 0; j < 16; j++) f[j] = __ldg(wpg + (size_t)j * N);
        uint32_t h[8], l[8];
        #pragma unroll
        for (int j = 0; j < 8; j++) split_pack(f[2*j], f[2*j+1], h[j], l[j]);
        char* pb0 = stg + PLANE + bn * ROWB + bkh * 32;
        *(uint4*)pb0           = make_uint4(h[0],h[1],h[2],h[3]);
        *(uint4*)(pb0 + 16)    = make_uint4(h[4],h[5],h[6],h[7]);
        *(uint4*)(pb0 + PLANE) = make_uint4(l[0],l[1],l[2],l[3]);
        *(uint4*)(pb0 + PLANE + 16) = make_uint4(l[4],l[5],l[6],l[7]);
    }
    __syncthreads();

    for (int c = 0; c < NC; c++) {
        const int cur = c & 1;
        const bool more = (c + 1 < NC);
        if (more) {
            const int k0 = (c + 1) * 32;
            const float* ap = apg + k0;
            pa[0] = *(const float4*)ap;       pa[1] = *(const float4*)(ap + 4);
            pa[2] = *(const float4*)(ap + 8); pa[3] = *(const float4*)(ap + 12);
            const float* wp = wpg + (size_t)k0 * N;
            #pragma unroll
            for (int j = 0; j < 16; j++) pb[j] = __ldg(wp + (size_t)j * N);
        }

        const uint32_t ab = a_base + cur * STAGE;
        const uint32_t bb = b_base + cur * STAGE;
        #pragma unroll
        for (int kk = 0; kk < 2; kk++) {
            uint32_t aH[2][4], bF[4][4];
            ldsm4(aH[0], ab + kk * 32);
            ldsm4(aH[1], ab + kk * 32 + 16 * ROWB);
            #pragma unroll
            for (int j2 = 0; j2 < 4; j2++) ldsm4(bF[j2], bb + kk * 32 + j2 * 16 * ROWB);
            #pragma unroll
            for (int mi = 0; mi < 2; mi++)
                #pragma unroll
                for (int j2 = 0; j2 < 4; j2++) {
                    mma16816(acc[mi][2*j2],   aH[mi], &bF[j2][0]);
                    mma16816(acc[mi][2*j2+1], aH[mi], &bF[j2][2]);
                }
            #pragma unroll
            for (int j2 = 0; j2 < 4; j2++) ldsm4(bF[j2], bb + PLANE + kk * 32 + j2 * 16 * ROWB);
            #pragma unroll
            for (int mi = 0; mi < 2; mi++)
                #pragma unroll
                for (int j2 = 0; j2 < 4; j2++) {
                    mma16816(acc[mi][2*j2],   aH[mi], &bF[j2][0]);
                    mma16816(acc[mi][2*j2+1], aH[mi], &bF[j2][2]);
                }
        }

        if (more) {
            char* nb = stg + (cur ^ 1) * STAGE;
            char* pa0 = nb + arow * ROWB + akh * 32;
            *(uint4*)pa0 = make_uint4(pack_h(pa[0].x,pa[0].y), pack_h(pa[0].z,pa[0].w),
                                      pack_h(pa[1].x,pa[1].y), pack_h(pa[1].z,pa[1].w));
            *(uint4*)(pa0 + 16) = make_uint4(pack_h(pa[2].x,pa[2].y), pack_h(pa[2].z,pa[2].w),
                                             pack_h(pa[3].x,pa[3].y), pack_h(pa[3].z,pa[3].w));
            uint32_t h[8], l[8];
            #pragma unroll
            for (int j = 0; j < 8; j++) split_pack(pb[2*j], pb[2*j+1], h[j], l[j]);
            char* pb0 = nb + PLANE + bn * ROWB + bkh * 32;
            *(uint4*)pb0           = make_uint4(h[0],h[1],h[2],h[3]);
            *(uint4*)(pb0 + 16)    = make_uint4(h[4],h[5],h[6],h[7]);
            *(uint4*)(pb0 + PLANE) = make_uint4(l[0],l[1],l[2],l[3]);
            *(uint4*)(pb0 + PLANE + 16) = make_uint4(l[4],l[5],l[6],l[7]);
        }
        __syncthreads();
    }

    // epilogue
    float b2x[8], b2y[8];
    int   hh[8], dd0[8];
    #pragma unroll
    for (int nj = 0; nj < 8; nj++) {
        const int col = n0 + wn * 64 + nj * 8 + (lane & 3) * 2;
        b2x[nj] = __ldg(&bias[col]);
        b2y[nj] = __ldg(&bias[col + 1]);
        if (IS_QKV) {
            const int h = col / 384, rem = col - h * 384;
            hh[nj] = h * 3 + (rem >> 7);
            dd0[nj] = rem & 127;
        }
    }
    #pragma unroll
    for (int mi = 0; mi < 2; mi++) {
        #pragma unroll
        for (int rr = 0; rr < 2; rr++) {
            const int row = m0 + wm * 32 + mi * 16 + (lane >> 2) + rr * 8;
            if (IS_QKV) {
                const int bbat = row >> 11, ss = row & 2047;
                #pragma unroll
                for (int nj = 0; nj < 8; nj++) {
                    const int h = hh[nj] / 3, comp = hh[nj] - h * 3;
                    float* dst = ((comp == 0) ? g_q : (comp == 1) ? g_k : g_v)
                               + ((size_t)(bbat * NH + h) * SEQ + ss) * HD + dd0[nj];
                    *(float2*)dst = make_float2(acc[mi][nj][rr*2] + b2x[nj],
                                                acc[mi][nj][rr*2+1] + b2y[nj]);
                }
            } else {
                const size_t o = (size_t)row * HID + n0 + wn * 64 + (lane & 3) * 2;
                #pragma unroll
                for (int nj = 0; nj < 8; nj++) {
                    float2 rv = *(const float2*)(resid + o + nj * 8);
                    *(float2*)(out + o + nj * 8) =
                        make_float2(acc[mi][nj][rr*2] + b2x[nj] + rv.x,
                                    acc[mi][nj][rr*2+1] + b2y[nj] + rv.y);
                }
            }
        }
    }
}

// ==================== tensor-core flash attention (fp16 2-pass) ============
// planes (row stride 272B, 128 rows): Qh | Kh (reused as P) | Kl | Vh | Vl
#define STR  272
#define PLN  (128*STR)
#define ATT_SMEM (5*PLN)

// single-plane loader (Q, with scale)
__device__ __forceinline__ void att_load1(const float* __restrict__ src,
                                          char* hi, float scale, int tid)
{
    const int r = tid >> 1, ch = (tid & 1) * 64;
    const float* p = src + (size_t)r * HD + ch;
    char* ph = hi + r * STR + ch * 2;
    #pragma unroll
    for (int i = 0; i < 8; i++) {
        float4 v0 = *(const float4*)(p + i * 8);
        float4 v1 = *(const float4*)(p + i * 8 + 4);
        *(uint4*)(ph + i * 16) = make_uint4(
            pack_h(v0.x*scale, v0.y*scale), pack_h(v0.z*scale, v0.w*scale),
            pack_h(v1.x*scale, v1.y*scale), pack_h(v1.z*scale, v1.w*scale));
    }
}
// hi/lo loader (K)
__device__ __forceinline__ void att_load2(const float* __restrict__ src,
                                          char* hi, char* lo, int tid)
{
    const int r = tid >> 1, ch = (tid & 1) * 64;
    const float* p = src + (size_t)r * HD + ch;
    char* ph = hi + r * STR + ch * 2;
    char* pl = lo + r * STR + ch * 2;
    #pragma unroll
    for (int i = 0; i < 8; i++) {
        float4 v0 = *(const float4*)(p + i * 8);
        float4 v1 = *(const float4*)(p + i * 8 + 4);
        uint32_t h0,h1,h2,h3,l0,l1,l2,l3;
        split_pack(v0.x, v0.y, h0, l0); split_pack(v0.z, v0.w, h1, l1);
        split_pack(v1.x, v1.y, h2, l2); split_pack(v1.z, v1.w, h3, l3);
        *(uint4*)(ph + i * 16) = make_uint4(h0,h1,h2,h3);
        *(uint4*)(pl + i * 16) = make_uint4(l0,l1,l2,l3);
    }
}
// V: load 128x128 fp32 and transpose into [d][key] hi/lo planes
__device__ __forceinline__ void att_load_vt(const float* __restrict__ src,
                                            char* hi, char* lo, int tid)
{
    const int kp = tid & 63;
    const int dg = tid >> 6;
    const float* p0 = src + (size_t)(2 * kp) * HD + dg * 32;
    const float* p1 = p0 + HD;
    #pragma unroll
    for (int i = 0; i < 8; i++) {
        float4 a = *(const float4*)(p0 + i * 4);
        float4 b = *(const float4*)(p1 + i * 4);
        const int d = dg * 32 + i * 4;
        uint32_t h, l;
        split_pack(a.x, b.x, h, l);
        *(uint32_t*)(hi + (d+0) * STR + kp * 4) = h;
        *(uint32_t*)(lo + (d+0) * STR + kp * 4) = l;
        split_pack(a.y, b.y, h, l);
        *(uint32_t*)(hi + (d+1) * STR + kp * 4) = h;
        *(uint32_t*)(lo + (d+1) * STR + kp * 4) = l;
        split_pack(a.z, b.z, h, l);
        *(uint32_t*)(hi + (d+2) * STR + kp * 4) = h;
        *(uint32_t*)(lo + (d+2) * STR + kp * 4) = l;
        split_pack(a.w, b.w, h, l);
        *(uint32_t*)(hi + (d+3) * STR + kp * 4) = h;
        *(uint32_t*)(lo + (d+3) * STR + kp * 4) = l;
    }
}

__global__ void __launch_bounds__(256, 1) attn_mma_kernel(const float* __restrict__ alibi)
{
    extern __shared__ __align__(16) char sm[];
    char* Qh = sm;
    char* Kh = sm + PLN;     // reused as P
    char* Kl = sm + 2*PLN;
    char* Vh = sm + 3*PLN;
    char* Vl = sm + 4*PLN;
    __shared__ float red_mx[2][128];
    __shared__ float red_sm[2][128];

    const int tid = threadIdx.x;
    const int wid = tid >> 5, lane = tid & 31;
    const int wm = wid >> 1, wn = wid & 1;
    const int qt = gridDim.x - 1 - blockIdx.x;
    const int bh = blockIdx.y;
    const int q0 = qt * 128;
    const float inv_norm = 0.088388347648318447f;

    att_load1(g_q + ((size_t)bh * SEQ + q0) * HD, Qh, inv_norm, tid);

    const uint32_t a_off = (uint32_t)(wm * 32 + (lane & 15)) * STR + ((lane >> 4) << 4);
    const uint32_t b_off = (uint32_t)(wn * 64 + (lane & 7) + ((lane >> 4) << 3)) * STR
                         + (((lane >> 3) & 1) << 4);
    const uint32_t qh_b = smem_u32(Qh) + a_off;
    const uint32_t kh_b = smem_u32(Kh) + b_off, kl_b = smem_u32(Kl) + b_off;
    const uint32_t vh_b = smem_u32(Vh) + b_off, vl_b = smem_u32(Vl) + b_off;
    const uint32_t ph_b = smem_u32(Kh) + a_off;

    float o[2][8][4];
    float m_[2][2], l_[2][2], corr[2][2];
    #pragma unroll
    for (int mi = 0; mi < 2; mi++)
        #pragma unroll
        for (int rr = 0; rr < 2; rr++) { m_[mi][rr] = -1e30f; l_[mi][rr] = 0.f; }
    #pragma unroll
    for (int mi = 0; mi < 2; mi++)
        #pragma unroll
        for (int nj = 0; nj < 8; nj++)
            #pragma unroll
            for (int r = 0; r < 4; r++) o[mi][nj][r] = 0.f;

    const float* albase = alibi + (size_t)bh * SEQ;
    const int rbase = wm * 32 + (lane >> 2);

    for (int kt = 0; kt <= qt; kt++) {
        const int k0 = kt * 128;
        __syncthreads();
        att_load2(g_k + ((size_t)bh * SEQ + k0) * HD, Kh, Kl, tid);
        att_load_vt(g_v + ((size_t)bh * SEQ + k0) * HD, Vh, Vl, tid);
        __syncthreads();

        // S = Q K^T (2-pass)
        float s[2][8][4];
        #pragma unroll
        for (int mi = 0; mi < 2; mi++)
            #pragma unroll
            for (int nj = 0; nj < 8; nj++)
                #pragma unroll
                for (int r = 0; r < 4; r++) s[mi][nj][r] = 0.f;
        #pragma unroll
        for (int kk = 0; kk < 8; kk++) {
            uint32_t aH[2][4], bF[4][4];
            ldsm4(aH[0], qh_b + kk * 32);
            ldsm4(aH[1], qh_b + kk * 32 + 16 * STR);
            #pragma unroll
            for (int j2 = 0; j2 < 4; j2++) ldsm4(bF[j2], kh_b + kk * 32 + j2 * 16 * STR);
            #pragma unroll
            for (int mi = 0; mi < 2; mi++)
                #pragma unroll
                for (int j2 = 0; j2 < 4; j2++) {
                    mma16816(s[mi][2*j2],   aH[mi], &bF[j2][0]);
                    mma16816(s[mi][2*j2+1], aH[mi], &bF[j2][2]);
                }
            #pragma unroll
            for (int j2 = 0; j2 < 4; j2++) ldsm4(bF[j2], kl_b + kk * 32 + j2 * 16 * STR);
            #pragma unroll
            for (int mi = 0; mi < 2; mi++)
                #pragma unroll
                for (int j2 = 0; j2 < 4; j2++) {
                    mma16816(s[mi][2*j2],   aH[mi], &bF[j2][0]);
                    mma16816(s[mi][2*j2+1], aH[mi], &bF[j2][2]);
                }
        }

        // alibi + causal mask + partial row max
        float al[8][2];
        #pragma unroll
        for (int nj = 0; nj < 8; nj++) {
            const int col = k0 + wn * 64 + nj * 8 + (lane & 3) * 2;
            al[nj][0] = __ldg(albase + col);
            al[nj][1] = __ldg(albase + col + 1);
        }
        const bool diag = (kt == qt);
        #pragma unroll
        for (int mi = 0; mi < 2; mi++) {
            #pragma unroll
            for (int rr = 0; rr < 2; rr++) {
                const int rloc = rbase + mi * 16 + rr * 8;
                const int rowg = q0 + rloc;
                float mx = -1e30f;
                #pragma unroll
                for (int nj = 0; nj < 8; nj++) {
                    #pragma unroll
                    for (int e = 0; e < 2; e++) {
                        float v = s[mi][nj][rr*2+e] + al[nj][e];
                        if (diag && (k0 + wn*64 + nj*8 + (lane&3)*2 + e) > rowg) v = -1e30f;
                        s[mi][nj][rr*2+e] = v;
                        mx = fmaxf(mx, v);
                    }
                }
                mx = fmaxf(mx, __shfl_xor_sync(0xffffffffu, mx, 1));
                mx = fmaxf(mx, __shfl_xor_sync(0xffffffffu, mx, 2));
                if ((lane & 3) == 0) red_mx[wn][rloc] = mx;
            }
        }
        __syncthreads();

        // softmax
        #pragma unroll
        for (int mi = 0; mi < 2; mi++) {
            #pragma unroll
            for (int rr = 0; rr < 2; rr++) {
                const int rloc = rbase + mi * 16 + rr * 8;
                const float mx = fmaxf(red_mx[0][rloc], red_mx[1][rloc]);
                const float mnew = fmaxf(m_[mi][rr], mx);
                const float cr = __expf(m_[mi][rr] - mnew);
                corr[mi][rr] = cr;
                m_[mi][rr] = mnew;
                float ls = 0.f;
                #pragma unroll
                for (int nj = 0; nj < 8; nj++) {
                    #pragma unroll
                    for (int e = 0; e < 2; e++) {
                        float p = __expf(s[mi][nj][rr*2+e] - mnew);
                        s[mi][nj][rr*2+e] = p;
                        ls += p;
                    }
                }
                ls += __shfl_xor_sync(0xffffffffu, ls, 1);
                ls += __shfl_xor_sync(0xffffffffu, ls, 2);
                if ((lane & 3) == 0) red_sm[wn][rloc] = ls;
                #pragma unroll
                for (int nj = 0; nj < 8; nj++) {
                    o[mi][nj][rr*2]   *= cr;
                    o[mi][nj][rr*2+1] *= cr;
                }
            }
        }
        __syncthreads();
        #pragma unroll
        for (int mi = 0; mi < 2; mi++)
            #pragma unroll
            for (int rr = 0; rr < 2; rr++) {
                const int rloc = rbase + mi * 16 + rr * 8;
                l_[mi][rr] = l_[mi][rr] * corr[mi][rr] + red_sm[0][rloc] + red_sm[1][rloc];
            }

        // write P (single fp16) into Kh plane
        #pragma unroll
        for (int mi = 0; mi < 2; mi++) {
            #pragma unroll
            for (int rr = 0; rr < 2; rr++) {
                const uint32_t roff = (uint32_t)(rbase + mi * 16 + rr * 8) * STR
                                    + (wn * 64 + (lane & 3) * 2) * 2;
                #pragma unroll
                for (int nj = 0; nj < 8; nj++)
                    *(uint32_t*)(Kh + roff + nj * 16) =
                        pack_h(s[mi][nj][rr*2], s[mi][nj][rr*2+1]);
            }
        }
        __syncthreads();

        // O += P V (2-pass)
        #pragma unroll
        for (int kk = 0; kk < 8; kk++) {
            uint32_t aH[2][4], bF[4][4];
            ldsm4(aH[0], ph_b + kk * 32);
            ldsm4(aH[1], ph_b + kk * 32 + 16 * STR);
            #pragma unroll
            for (int j2 = 0; j2 < 4; j2++) ldsm4(bF[j2], vh_b + kk * 32 + j2 * 16 * STR);
            #pragma unroll
            for (int mi = 0; mi < 2; mi++)
                #pragma unroll
                for (int j2 = 0; j2 < 4; j2++) {
                    mma16816(o[mi][2*j2],   aH[mi], &bF[j2][0]);
                    mma16816(o[mi][2*j2+1], aH[mi], &bF[j2][2]);
                }
            #pragma unroll
            for (int j2 = 0; j2 < 4; j2++) ldsm4(bF[j2], vl_b + kk * 32 + j2 * 16 * STR);
            #pragma unroll
            for (int mi = 0; mi < 2; mi++)
                #pragma unroll
                for (int j2 = 0; j2 < 4; j2++) {
                    mma16816(o[mi][2*j2],   aH[mi], &bF[j2][0]);
                    mma16816(o[mi][2*j2+1], aH[mi], &bF[j2][2]);
                }
        }
    }

    // epilogue
    const int b = bh >> 5, h = bh & 31;
    #pragma unroll
    for (int mi = 0; mi < 2; mi++) {
        #pragma unroll
        for (int rr = 0; rr < 2; rr++) {
            const float invl = 1.f / l_[mi][rr];
            const int srow = q0 + rbase + mi * 16 + rr * 8;
            float* op = g_ctx + ((size_t)(b * SEQ + srow)) * HID + h * HD
                      + wn * 64 + (lane & 3) * 2;
            #pragma unroll
            for (int nj = 0; nj < 8; nj++)
                *(float2*)(op + nj * 8) = make_float2(o[mi][nj][rr*2] * invl,
                                                      o[mi][nj][rr*2+1] * invl);
        }
    }
}

// =============================== launch ====================================
extern "C" void kernel_launch(void* const* d_in, const int* in_sizes, int n_in,
                              void* d_out, int out_size)
{
    const float* hs    = (const float*)d_in[0];
    const float* resid = (const float*)d_in[1];
    const float* alibi = (const float*)d_in[2];
    const float* Wqkv  = (const float*)d_in[4];
    const float* bqkv  = (const float*)d_in[5];
    const float* Wd    = (const float*)d_in[6];
    const float* bd    = (const float*)d_in[7];
    float* out = (float*)d_out;

    cudaFuncSetAttribute(gemm_mma_kernel<true>,
                         cudaFuncAttributeMaxDynamicSharedMemorySize, GEMM_SMEM);
    cudaFuncSetAttribute(gemm_mma_kernel<false>,
                         cudaFuncAttributeMaxDynamicSharedMemorySize, GEMM_SMEM);
    cudaFuncSetAttribute(attn_mma_kernel,
                         cudaFuncAttributeMaxDynamicSharedMemorySize, ATT_SMEM);

    gemm_mma_kernel<true><<<dim3(NQKV/128, MROWS/128), 256, GEMM_SMEM>>>(hs, Wqkv, bqkv, nullptr, nullptr);
    attn_mma_kernel<<<dim3(SEQ/128, BATCH*NH), 256, ATT_SMEM>>>(alibi);
    gemm_mma_kernel<false><<<dim3(HID/128, MROWS/128), 256, GEMM_SMEM>>>(nullptr, Wd, bd, resid, out);
}

// round 7
// speedup vs baseline: 4.5041x; 1.3284x over previous
#include <cuda_runtime.h>
#include <cuda_fp16.h>
#include <stdint.h>

#define HID   4096
#define SEQ   2048
#define BATCH 2
#define NH    32
#define HD    128
#define MROWS (BATCH*SEQ)
#define NQKV  (3*HID)

__device__ float g_q[(size_t)BATCH*NH*SEQ*HD];
__device__ float g_k[(size_t)BATCH*NH*SEQ*HD];
__device__ float g_v[(size_t)BATCH*NH*SEQ*HD];
__device__ float g_ctx[(size_t)BATCH*SEQ*HID];

// ============================ helpers ======================================
__device__ __forceinline__ uint32_t smem_u32(const void* p) {
    uint32_t a;
    asm("{ .reg .u64 t; cvta.to.shared.u64 t, %1; cvt.u32.u64 %0, t; }" : "=r"(a) : "l"(p));
    return a;
}
__device__ __forceinline__ void ldsm4(uint32_t* r, uint32_t addr) {
    asm volatile("ldmatrix.sync.aligned.m8n8.x4.shared.b16 {%0,%1,%2,%3}, [%4];"
                 : "=r"(r[0]), "=r"(r[1]), "=r"(r[2]), "=r"(r[3]) : "r"(addr));
}
__device__ __forceinline__ void mma16816(float* d, const uint32_t* a, const uint32_t* b) {
    asm volatile("mma.sync.aligned.m16n8k16.row.col.f32.f16.f16.f32 "
                 "{%0,%1,%2,%3}, {%4,%5,%6,%7}, {%8,%9}, {%0,%1,%2,%3};"
                 : "+f"(d[0]), "+f"(d[1]), "+f"(d[2]), "+f"(d[3])
                 : "r"(a[0]), "r"(a[1]), "r"(a[2]), "r"(a[3]), "r"(b[0]), "r"(b[1]));
}
__device__ __forceinline__ uint32_t pack_h(float a, float b) {
    __half2 hh = __floats2half2_rn(a, b);
    return *(uint32_t*)&hh;
}

// ====================== fp16 single-pass GEMM ==============================
// stage: Ah@0 (10240) | Bh@10240 ; 80B row stride (32 k * 2B + pad)
#define ROWB   80
#define PLANE  10240
#define STAGE  20480
#define GEMM_SMEM (2 * STAGE)

template <bool IS_QKV>
__global__ void __launch_bounds__(256, 2)
gemm_mma_kernel(const float* __restrict__ Ain, const float* __restrict__ W,
                const float* __restrict__ bias, const float* __restrict__ resid,
                float* __restrict__ out)
{
    constexpr int N  = IS_QKV ? NQKV : HID;
    constexpr int NC = HID / 32;
    extern __shared__ __align__(16) char stg[];
    const uint32_t stg_u = smem_u32(stg);

    const float* A = IS_QKV ? Ain : (const float*)g_ctx;
    const int tid  = threadIdx.x;
    const int wid  = tid >> 5, lane = tid & 31;
    const int wm   = wid >> 1, wn = wid & 1;
    const int m0   = blockIdx.y * 128, n0 = blockIdx.x * 128;

    const int arow = tid >> 1, akh = tid & 1;
    const int bn   = tid & 127, bkh = tid >> 7;
    const float* apg = A + (size_t)(m0 + arow) * HID + akh * 16;
    const float* wpg = W + (size_t)(bkh * 16) * N + n0 + bn;

    float acc[2][8][4];
    #pragma unroll
    for (int mi = 0; mi < 2; mi++)
        #pragma unroll
        for (int nj = 0; nj < 8; nj++)
            #pragma unroll
            for (int r = 0; r < 4; r++) acc[mi][nj][r] = 0.f;

    float4 pa[4];
    float  pb[16];

    const uint32_t a_base = stg_u + (uint32_t)(wm * 32 + (lane & 15)) * ROWB + ((lane >> 4) << 4);
    const uint32_t b_base = stg_u + PLANE
                          + (uint32_t)(wn * 64 + (lane & 7) + ((lane >> 4) << 3)) * ROWB
                          + (((lane >> 3) & 1) << 4);

    // prologue: chunk 0
    {
        const float* ap = apg;
        float4 q0 = *(const float4*)ap, q1 = *(const float4*)(ap + 4);
        float4 q2 = *(const float4*)(ap + 8), q3 = *(const float4*)(ap + 12);
        char* pa0 = stg + arow * ROWB + akh * 32;
        *(uint4*)pa0 = make_uint4(pack_h(q0.x,q0.y), pack_h(q0.z,q0.w),
                                  pack_h(q1.x,q1.y), pack_h(q1.z,q1.w));
        *(uint4*)(pa0 + 16) = make_uint4(pack_h(q2.x,q2.y), pack_h(q2.z,q2.w),
                                         pack_h(q3.x,q3.y), pack_h(q3.z,q3.w));
        float f[16];
        #pragma unroll
        for (int j = 0; j < 16; j++) f[j] = __ldg(wpg + (size_t)j * N);
        char* pb0 = stg + PLANE + bn * ROWB + bkh * 32;
        *(uint4*)pb0 = make_uint4(pack_h(f[0],f[1]), pack_h(f[2],f[3]),
                                  pack_h(f[4],f[5]), pack_h(f[6],f[7]));
        *(uint4*)(pb0 + 16) = make_uint4(pack_h(f[8],f[9]),  pack_h(f[10],f[11]),
                                         pack_h(f[12],f[13]), pack_h(f[14],f[15]));
    }
    __syncthreads();

    for (int c = 0; c < NC; c++) {
        const int cur = c & 1;
        const bool more = (c + 1 < NC);
        if (more) {
            const int k0 = (c + 1) * 32;
            const float* ap = apg + k0;
            pa[0] = *(const float4*)ap;       pa[1] = *(const float4*)(ap + 4);
            pa[2] = *(const float4*)(ap + 8); pa[3] = *(const float4*)(ap + 12);
            const float* wp = wpg + (size_t)k0 * N;
            #pragma unroll
            for (int j = 0; j < 16; j++) pb[j] = __ldg(wp + (size_t)j * N);
        }

        const uint32_t ab = a_base + cur * STAGE;
        const uint32_t bb = b_base + cur * STAGE;
        #pragma unroll
        for (int kk = 0; kk < 2; kk++) {
            uint32_t aH[2][4], bF[4][4];
            ldsm4(aH[0], ab + kk * 32);
            ldsm4(aH[1], ab + kk * 32 + 16 * ROWB);
            #pragma unroll
            for (int j2 = 0; j2 < 4; j2++) ldsm4(bF[j2], bb + kk * 32 + j2 * 16 * ROWB);
            #pragma unroll
            for (int mi = 0; mi < 2; mi++)
                #pragma unroll
                for (int j2 = 0; j2 < 4; j2++) {
                    mma16816(acc[mi][2*j2],   aH[mi], &bF[j2][0]);
                    mma16816(acc[mi][2*j2+1], aH[mi], &bF[j2][2]);
                }
        }

        if (more) {
            char* nb = stg + (cur ^ 1) * STAGE;
            char* pa0 = nb + arow * ROWB + akh * 32;
            *(uint4*)pa0 = make_uint4(pack_h(pa[0].x,pa[0].y), pack_h(pa[0].z,pa[0].w),
                                      pack_h(pa[1].x,pa[1].y), pack_h(pa[1].z,pa[1].w));
            *(uint4*)(pa0 + 16) = make_uint4(pack_h(pa[2].x,pa[2].y), pack_h(pa[2].z,pa[2].w),
                                             pack_h(pa[3].x,pa[3].y), pack_h(pa[3].z,pa[3].w));
            char* pb0 = nb + PLANE + bn * ROWB + bkh * 32;
            *(uint4*)pb0 = make_uint4(pack_h(pb[0],pb[1]), pack_h(pb[2],pb[3]),
                                      pack_h(pb[4],pb[5]), pack_h(pb[6],pb[7]));
            *(uint4*)(pb0 + 16) = make_uint4(pack_h(pb[8],pb[9]),  pack_h(pb[10],pb[11]),
                                             pack_h(pb[12],pb[13]), pack_h(pb[14],pb[15]));
        }
        __syncthreads();
    }

    // epilogue
    float b2x[8], b2y[8];
    int   hh[8], dd0[8];
    #pragma unroll
    for (int nj = 0; nj < 8; nj++) {
        const int col = n0 + wn * 64 + nj * 8 + (lane & 3) * 2;
        b2x[nj] = __ldg(&bias[col]);
        b2y[nj] = __ldg(&bias[col + 1]);
        if (IS_QKV) {
            const int h = col / 384, rem = col - h * 384;
            hh[nj] = h * 3 + (rem >> 7);
            dd0[nj] = rem & 127;
        }
    }
    #pragma unroll
    for (int mi = 0; mi < 2; mi++) {
        #pragma unroll
        for (int rr = 0; rr < 2; rr++) {
            const int row = m0 + wm * 32 + mi * 16 + (lane >> 2) + rr * 8;
            if (IS_QKV) {
                const int bbat = row >> 11, ss = row & 2047;
                #pragma unroll
                for (int nj = 0; nj < 8; nj++) {
                    const int h = hh[nj] / 3, comp = hh[nj] - h * 3;
                    float* dst = ((comp == 0) ? g_q : (comp == 1) ? g_k : g_v)
                               + ((size_t)(bbat * NH + h) * SEQ + ss) * HD + dd0[nj];
                    *(float2*)dst = make_float2(acc[mi][nj][rr*2] + b2x[nj],
                                                acc[mi][nj][rr*2+1] + b2y[nj]);
                }
            } else {
                const size_t o = (size_t)row * HID + n0 + wn * 64 + (lane & 3) * 2;
                #pragma unroll
                for (int nj = 0; nj < 8; nj++) {
                    float2 rv = *(const float2*)(resid + o + nj * 8);
                    *(float2*)(out + o + nj * 8) =
                        make_float2(acc[mi][nj][rr*2] + b2x[nj] + rv.x,
                                    acc[mi][nj][rr*2+1] + b2y[nj] + rv.y);
                }
            }
        }
    }
}

// ==================== tensor-core flash attention (fp16 1-pass) ============
// planes (row stride 272B, 128 rows): Qh | Kh (reused as P) | Vh
#define STR  272
#define PLN  (128*STR)
#define ATT_SMEM (3*PLN)

// single-plane loader (Q/K, optional scale)
__device__ __forceinline__ void att_load1(const float* __restrict__ src,
                                          char* hi, float scale, int tid)
{
    const int r = tid >> 1, ch = (tid & 1) * 64;
    const float* p = src + (size_t)r * HD + ch;
    char* ph = hi + r * STR + ch * 2;
    #pragma unroll
    for (int i = 0; i < 8; i++) {
        float4 v0 = *(const float4*)(p + i * 8);
        float4 v1 = *(const float4*)(p + i * 8 + 4);
        *(uint4*)(ph + i * 16) = make_uint4(
            pack_h(v0.x*scale, v0.y*scale), pack_h(v0.z*scale, v0.w*scale),
            pack_h(v1.x*scale, v1.y*scale), pack_h(v1.z*scale, v1.w*scale));
    }
}
// V: load 128x128 fp32 and transpose into [d][key] plane
__device__ __forceinline__ void att_load_vt(const float* __restrict__ src,
                                            char* hi, int tid)
{
    const int kp = tid & 63;
    const int dg = tid >> 6;
    const float* p0 = src + (size_t)(2 * kp) * HD + dg * 32;
    const float* p1 = p0 + HD;
    #pragma unroll
    for (int i = 0; i < 8; i++) {
        float4 a = *(const float4*)(p0 + i * 4);
        float4 b = *(const float4*)(p1 + i * 4);
        const int d = dg * 32 + i * 4;
        *(uint32_t*)(hi + (d+0) * STR + kp * 4) = pack_h(a.x, b.x);
        *(uint32_t*)(hi + (d+1) * STR + kp * 4) = pack_h(a.y, b.y);
        *(uint32_t*)(hi + (d+2) * STR + kp * 4) = pack_h(a.z, b.z);
        *(uint32_t*)(hi + (d+3) * STR + kp * 4) = pack_h(a.w, b.w);
    }
}

__global__ void __launch_bounds__(256, 1) attn_mma_kernel(const float* __restrict__ alibi)
{
    extern __shared__ __align__(16) char sm[];
    char* Qh = sm;
    char* Kh = sm + PLN;     // reused as P
    char* Vh = sm + 2*PLN;
    __shared__ float red_mx[2][128];
    __shared__ float red_sm[2][128];

    const int tid = threadIdx.x;
    const int wid = tid >> 5, lane = tid & 31;
    const int wm = wid >> 1, wn = wid & 1;
    const int qt = gridDim.x - 1 - blockIdx.x;
    const int bh = blockIdx.y;
    const int q0 = qt * 128;
    const float inv_norm = 0.088388347648318447f;

    att_load1(g_q + ((size_t)bh * SEQ + q0) * HD, Qh, inv_norm, tid);

    const uint32_t a_off = (uint32_t)(wm * 32 + (lane & 15)) * STR + ((lane >> 4) << 4);
    const uint32_t b_off = (uint32_t)(wn * 64 + (lane & 7) + ((lane >> 4) << 3)) * STR
                         + (((lane >> 3) & 1) << 4);
    const uint32_t qh_b = smem_u32(Qh) + a_off;
    const uint32_t kh_b = smem_u32(Kh) + b_off;
    const uint32_t vh_b = smem_u32(Vh) + b_off;
    const uint32_t ph_b = smem_u32(Kh) + a_off;

    float o[2][8][4];
    float m_[2][2], l_[2][2], corr[2][2];
    #pragma unroll
    for (int mi = 0; mi < 2; mi++)
        #pragma unroll
        for (int rr = 0; rr < 2; rr++) { m_[mi][rr] = -1e30f; l_[mi][rr] = 0.f; }
    #pragma unroll
    for (int mi = 0; mi < 2; mi++)
        #pragma unroll
        for (int nj = 0; nj < 8; nj++)
            #pragma unroll
            for (int r = 0; r < 4; r++) o[mi][nj][r] = 0.f;

    const float* albase = alibi + (size_t)bh * SEQ;
    const int rbase = wm * 32 + (lane >> 2);

    for (int kt = 0; kt <= qt; kt++) {
        const int k0 = kt * 128;
        __syncthreads();
        att_load1(g_k + ((size_t)bh * SEQ + k0) * HD, Kh, 1.f, tid);
        att_load_vt(g_v + ((size_t)bh * SEQ + k0) * HD, Vh, tid);
        __syncthreads();

        // S = Q K^T
        float s[2][8][4];
        #pragma unroll
        for (int mi = 0; mi < 2; mi++)
            #pragma unroll
            for (int nj = 0; nj < 8; nj++)
                #pragma unroll
                for (int r = 0; r < 4; r++) s[mi][nj][r] = 0.f;
        #pragma unroll
        for (int kk = 0; kk < 8; kk++) {
            uint32_t aH[2][4], bF[4][4];
            ldsm4(aH[0], qh_b + kk * 32);
            ldsm4(aH[1], qh_b + kk * 32 + 16 * STR);
            #pragma unroll
            for (int j2 = 0; j2 < 4; j2++) ldsm4(bF[j2], kh_b + kk * 32 + j2 * 16 * STR);
            #pragma unroll
            for (int mi = 0; mi < 2; mi++)
                #pragma unroll
                for (int j2 = 0; j2 < 4; j2++) {
                    mma16816(s[mi][2*j2],   aH[mi], &bF[j2][0]);
                    mma16816(s[mi][2*j2+1], aH[mi], &bF[j2][2]);
                }
        }

        // alibi + causal mask + partial row max
        float al[8][2];
        #pragma unroll
        for (int nj = 0; nj < 8; nj++) {
            const int col = k0 + wn * 64 + nj * 8 + (lane & 3) * 2;
            al[nj][0] = __ldg(albase + col);
            al[nj][1] = __ldg(albase + col + 1);
        }
        const bool diag = (kt == qt);
        #pragma unroll
        for (int mi = 0; mi < 2; mi++) {
            #pragma unroll
            for (int rr = 0; rr < 2; rr++) {
                const int rloc = rbase + mi * 16 + rr * 8;
                const int rowg = q0 + rloc;
                float mx = -1e30f;
                #pragma unroll
                for (int nj = 0; nj < 8; nj++) {
                    #pragma unroll
                    for (int e = 0; e < 2; e++) {
                        float v = s[mi][nj][rr*2+e] + al[nj][e];
                        if (diag && (k0 + wn*64 + nj*8 + (lane&3)*2 + e) > rowg) v = -1e30f;
                        s[mi][nj][rr*2+e] = v;
                        mx = fmaxf(mx, v);
                    }
                }
                mx = fmaxf(mx, __shfl_xor_sync(0xffffffffu, mx, 1));
                mx = fmaxf(mx, __shfl_xor_sync(0xffffffffu, mx, 2));
                if ((lane & 3) == 0) red_mx[wn][rloc] = mx;
            }
        }
        __syncthreads();

        // softmax
        #pragma unroll
        for (int mi = 0; mi < 2; mi++) {
            #pragma unroll
            for (int rr = 0; rr < 2; rr++) {
                const int rloc = rbase + mi * 16 + rr * 8;
                const float mx = fmaxf(red_mx[0][rloc], red_mx[1][rloc]);
                const float mnew = fmaxf(m_[mi][rr], mx);
                const float cr = __expf(m_[mi][rr] - mnew);
                corr[mi][rr] = cr;
                m_[mi][rr] = mnew;
                float ls = 0.f;
                #pragma unroll
                for (int nj = 0; nj < 8; nj++) {
                    #pragma unroll
                    for (int e = 0; e < 2; e++) {
                        float p = __expf(s[mi][nj][rr*2+e] - mnew);
                        s[mi][nj][rr*2+e] = p;
                        ls += p;
                    }
                }
                ls += __shfl_xor_sync(0xffffffffu, ls, 1);
                ls += __shfl_xor_sync(0xffffffffu, ls, 2);
                if ((lane & 3) == 0) red_sm[wn][rloc] = ls;
                #pragma unroll
                for (int nj = 0; nj < 8; nj++) {
                    o[mi][nj][rr*2]   *= cr;
                    o[mi][nj][rr*2+1] *= cr;
                }
            }
        }
        __syncthreads();
        #pragma unroll
        for (int mi = 0; mi < 2; mi++)
            #pragma unroll
            for (int rr = 0; rr < 2; rr++) {
                const int rloc = rbase + mi * 16 + rr * 8;
                l_[mi][rr] = l_[mi][rr] * corr[mi][rr] + red_sm[0][rloc] + red_sm[1][rloc];
            }

        // write P (fp16) into Kh plane
        #pragma unroll
        for (int mi = 0; mi < 2; mi++) {
            #pragma unroll
            for (int rr = 0; rr < 2; rr++) {
                const uint32_t roff = (uint32_t)(rbase + mi * 16 + rr * 8) * STR
                                    + (wn * 64 + (lane & 3) * 2) * 2;
                #pragma unroll
                for (int nj = 0; nj < 8; nj++)
                    *(uint32_t*)(Kh + roff + nj * 16) =
                        pack_h(s[mi][nj][rr*2], s[mi][nj][rr*2+1]);
            }
        }
        __syncthreads();

        // O += P V
        #pragma unroll
        for (int kk = 0; kk < 8; kk++) {
            uint32_t aH[2][4], bF[4][4];
            ldsm4(aH[0], ph_b + kk * 32);
            ldsm4(aH[1], ph_b + kk * 32 + 16 * STR);
            #pragma unroll
            for (int j2 = 0; j2 < 4; j2++) ldsm4(bF[j2], vh_b + kk * 32 + j2 * 16 * STR);
            #pragma unroll
            for (int mi = 0; mi < 2; mi++)
                #pragma unroll
                for (int j2 = 0; j2 < 4; j2++) {
                    mma16816(o[mi][2*j2],   aH[mi], &bF[j2][0]);
                    mma16816(o[mi][2*j2+1], aH[mi], &bF[j2][2]);
                }
        }
    }

    // epilogue
    const int b = bh >> 5, h = bh & 31;
    #pragma unroll
    for (int mi = 0; mi < 2; mi++) {
        #pragma unroll
        for (int rr = 0; rr < 2; rr++) {
            const float invl = 1.f / l_[mi][rr];
            const int srow = q0 + rbase + mi * 16 + rr * 8;
            float* op = g_ctx + ((size_t)(b * SEQ + srow)) * HID + h * HD
                      + wn * 64 + (lane & 3) * 2;
            #pragma unroll
            for (int nj = 0; nj < 8; nj++)
                *(float2*)(op + nj * 8) = make_float2(o[mi][nj][rr*2] * invl,
                                                      o[mi][nj][rr*2+1] * invl);
        }
    }
}

// =============================== launch ====================================
extern "C" void kernel_launch(void* const* d_in, const int* in_sizes, int n_in,
                              void* d_out, int out_size)
{
    const float* hs    = (const float*)d_in[0];
    const float* resid = (const float*)d_in[1];
    const float* alibi = (const float*)d_in[2];
    const float* Wqkv  = (const float*)d_in[4];
    const float* bqkv  = (const float*)d_in[5];
    const float* Wd    = (const float*)d_in[6];
    const float* bd    = (const float*)d_in[7];
    float* out = (float*)d_out;

    cudaFuncSetAttribute(gemm_mma_kernel<true>,
                         cudaFuncAttributeMaxDynamicSharedMemorySize, GEMM_SMEM);
    cudaFuncSetAttribute(gemm_mma_kernel<false>,
                         cudaFuncAttributeMaxDynamicSharedMemorySize, GEMM_SMEM);
    cudaFuncSetAttribute(attn_mma_kernel,
                         cudaFuncAttributeMaxDynamicSharedMemorySize, ATT_SMEM);

    gemm_mma_kernel<true><<<dim3(NQKV/128, MROWS/128), 256, GEMM_SMEM>>>(hs, Wqkv, bqkv, nullptr, nullptr);
    attn_mma_kernel<<<dim3(SEQ/128, BATCH*NH), 256, ATT_SMEM>>>(alibi);
    gemm_mma_kernel<false><<<dim3(HID/128, MROWS/128), 256, GEMM_SMEM>>>(nullptr, Wd, bd, resid, out);
}

// round 8
// speedup vs baseline: 5.0975x; 1.1317x over previous
#include <cuda_runtime.h>
#include <cuda_fp16.h>
#include <stdint.h>

#define HID   4096
#define SEQ   2048
#define BATCH 2
#define NH    32
#define HD    128
#define MROWS (BATCH*SEQ)
#define NQKV  (3*HID)

// fp16 scratch (device globals)
__device__ __half g_ah  [(size_t)MROWS*HID];          // hs fp16
__device__ __half g_wqkvT[(size_t)NQKV*HID];          // Wqkv^T fp16 [n][k]
__device__ __half g_wdT [(size_t)HID*HID];            // Wd^T fp16 [n][k]
__device__ __half g_qh  [(size_t)BATCH*NH*SEQ*HD];    // q fp16, pre-scaled
__device__ __half g_kh  [(size_t)BATCH*NH*SEQ*HD];    // k fp16
__device__ __half g_vT  [(size_t)BATCH*NH*HD*SEQ];    // v fp16 transposed [bh][d][s]
__device__ __half g_ctxh[(size_t)MROWS*HID];          // ctx fp16

// ============================ helpers ======================================
__device__ __forceinline__ uint32_t smem_u32(const void* p) {
    uint32_t a;
    asm("{ .reg .u64 t; cvta.to.shared.u64 t, %1; cvt.u32.u64 %0, t; }" : "=r"(a) : "l"(p));
    return a;
}
__device__ __forceinline__ void ldsm4(uint32_t* r, uint32_t addr) {
    asm volatile("ldmatrix.sync.aligned.m8n8.x4.shared.b16 {%0,%1,%2,%3}, [%4];"
                 : "=r"(r[0]), "=r"(r[1]), "=r"(r[2]), "=r"(r[3]) : "r"(addr));
}
__device__ __forceinline__ void mma16816(float* d, const uint32_t* a, const uint32_t* b) {
    asm volatile("mma.sync.aligned.m16n8k16.row.col.f32.f16.f16.f32 "
                 "{%0,%1,%2,%3}, {%4,%5,%6,%7}, {%8,%9}, {%0,%1,%2,%3};"
                 : "+f"(d[0]), "+f"(d[1]), "+f"(d[2]), "+f"(d[3])
                 : "r"(a[0]), "r"(a[1]), "r"(a[2]), "r"(a[3]), "r"(b[0]), "r"(b[1]));
}
__device__ __forceinline__ uint32_t pack_h(float a, float b) {
    __half2 hh = __floats2half2_rn(a, b);
    return *(uint32_t*)&hh;
}

// ===================== conversion prologue kernels =========================
__global__ void conv_fp16_kernel(const float* __restrict__ src,
                                 __half* __restrict__ dst, int n4)
{
    const int i = blockIdx.x * blockDim.x + threadIdx.x;
    if (i < n4) {
        float4 v = ((const float4*)src)[i];
        uint2 o;
        o.x = pack_h(v.x, v.y);
        o.y = pack_h(v.z, v.w);
        ((uint2*)dst)[i] = o;
    }
}
// src [R][C] fp32 -> dst [C][R] fp16  (block 32x8, 32x32 tile)
__global__ void transpose_fp16_kernel(const float* __restrict__ src,
                                      __half* __restrict__ dst, int R, int C)
{
    __shared__ float t[32][33];
    const int x = blockIdx.x * 32 + threadIdx.x;
    const int y0 = blockIdx.y * 32;
    #pragma unroll
    for (int j = 0; j < 4; j++)
        t[threadIdx.y + j * 8][threadIdx.x] = src[(size_t)(y0 + threadIdx.y + j * 8) * C + x];
    __syncthreads();
    const int xo = y0 + threadIdx.x;
    const int yo0 = blockIdx.x * 32;
    #pragma unroll
    for (int j = 0; j < 4; j++)
        dst[(size_t)(yo0 + threadIdx.y + j * 8) * R + xo] =
            __float2half(t[threadIdx.x][threadIdx.y + j * 8]);
}

// ====================== fp16 single-pass GEMM ==============================
// stage: A@0 (10240) | B@10240 ; 80B row stride
#define ROWB   80
#define PLANE  10240
#define STAGE  20480
#define GEMM_SMEM (2 * STAGE)

template <bool IS_QKV>
__global__ void __launch_bounds__(256, 2)
gemm_mma_kernel(const __half* __restrict__ Ah, const __half* __restrict__ Wt,
                const float* __restrict__ bias, const float* __restrict__ resid,
                float* __restrict__ out)
{
    constexpr int NC = HID / 32;
    extern __shared__ __align__(16) char stg[];
    const uint32_t stg_u = smem_u32(stg);

    const int tid  = threadIdx.x;
    const int wid  = tid >> 5, lane = tid & 31;
    const int wm   = wid >> 1, wn = wid & 1;
    const int m0   = blockIdx.y * 128, n0 = blockIdx.x * 128;

    // loader: thread -> (row = tid>>1, 32B seg = (tid&1)*16 halves)
    const int lrow = tid >> 1, lseg = (tid & 1) * 16;
    const __half* aP = Ah + (size_t)(m0 + lrow) * HID + lseg;
    const __half* bP = Wt + (size_t)(n0 + lrow) * HID + lseg;
    char* sA = stg + lrow * ROWB + lseg * 2;
    char* sB = stg + PLANE + lrow * ROWB + lseg * 2;

    float acc[2][8][4];
    #pragma unroll
    for (int mi = 0; mi < 2; mi++)
        #pragma unroll
        for (int nj = 0; nj < 8; nj++)
            #pragma unroll
            for (int r = 0; r < 4; r++) acc[mi][nj][r] = 0.f;

    uint4 pA0, pA1, pB0, pB1;

    const uint32_t a_base = stg_u + (uint32_t)(wm * 32 + (lane & 15)) * ROWB + ((lane >> 4) << 4);
    const uint32_t b_base = stg_u + PLANE
                          + (uint32_t)(wn * 64 + (lane & 7) + ((lane >> 4) << 3)) * ROWB
                          + (((lane >> 3) & 1) << 4);

    // prologue: chunk 0
    *(uint4*)sA        = *(const uint4*)aP;
    *(uint4*)(sA + 16) = *(const uint4*)(aP + 8);
    *(uint4*)sB        = *(const uint4*)bP;
    *(uint4*)(sB + 16) = *(const uint4*)(bP + 8);
    __syncthreads();

    for (int c = 0; c < NC; c++) {
        const int cur = c & 1;
        const bool more = (c + 1 < NC);
        if (more) {
            const int k0 = (c + 1) * 32;
            pA0 = *(const uint4*)(aP + k0);
            pA1 = *(const uint4*)(aP + k0 + 8);
            pB0 = *(const uint4*)(bP + k0);
            pB1 = *(const uint4*)(bP + k0 + 8);
        }

        const uint32_t ab = a_base + cur * STAGE;
        const uint32_t bb = b_base + cur * STAGE;
        #pragma unroll
        for (int kk = 0; kk < 2; kk++) {
            uint32_t aH[2][4], bF[4][4];
            ldsm4(aH[0], ab + kk * 32);
            ldsm4(aH[1], ab + kk * 32 + 16 * ROWB);
            #pragma unroll
            for (int j2 = 0; j2 < 4; j2++) ldsm4(bF[j2], bb + kk * 32 + j2 * 16 * ROWB);
            #pragma unroll
            for (int mi = 0; mi < 2; mi++)
                #pragma unroll
                for (int j2 = 0; j2 < 4; j2++) {
                    mma16816(acc[mi][2*j2],   aH[mi], &bF[j2][0]);
                    mma16816(acc[mi][2*j2+1], aH[mi], &bF[j2][2]);
                }
        }

        if (more) {
            const int nb = (cur ^ 1) * STAGE;
            *(uint4*)(sA + nb)      = pA0;
            *(uint4*)(sA + nb + 16) = pA1;
            *(uint4*)(sB + nb)      = pB0;
            *(uint4*)(sB + nb + 16) = pB1;
        }
        __syncthreads();
    }

    // ---------------------------- epilogue ---------------------------------
    const float inv_norm = 0.088388347648318447f;
    float b2x[8], b2y[8];
    #pragma unroll
    for (int nj = 0; nj < 8; nj++) {
        const int col = n0 + wn * 64 + nj * 8 + (lane & 3) * 2;
        b2x[nj] = __ldg(&bias[col]);
        b2y[nj] = __ldg(&bias[col + 1]);
    }
    if (IS_QKV) {
        const int h = blockIdx.x / 3, comp = blockIdx.x % 3;
        #pragma unroll
        for (int mi = 0; mi < 2; mi++) {
            #pragma unroll
            for (int rr = 0; rr < 2; rr++) {
                const int row = m0 + wm * 32 + mi * 16 + (lane >> 2) + rr * 8;
                const int bbat = row >> 11, ss = row & 2047;
                #pragma unroll
                for (int nj = 0; nj < 8; nj++) {
                    const int d = wn * 64 + nj * 8 + (lane & 3) * 2;
                    float vx = acc[mi][nj][rr*2]   + b2x[nj];
                    float vy = acc[mi][nj][rr*2+1] + b2y[nj];
                    if (comp == 0) {
                        __half* dst = g_qh + ((size_t)(bbat * NH + h) * SEQ + ss) * HD + d;
                        *(uint32_t*)dst = pack_h(vx * inv_norm, vy * inv_norm);
                    } else if (comp == 1) {
                        __half* dst = g_kh + ((size_t)(bbat * NH + h) * SEQ + ss) * HD + d;
                        *(uint32_t*)dst = pack_h(vx, vy);
                    } else {
                        __half* dst = g_vT + ((size_t)(bbat * NH + h) * HD + d) * SEQ + ss;
                        dst[0]   = __float2half(vx);
                        dst[SEQ] = __float2half(vy);
                    }
                }
            }
        }
    } else {
        #pragma unroll
        for (int mi = 0; mi < 2; mi++) {
            #pragma unroll
            for (int rr = 0; rr < 2; rr++) {
                const int row = m0 + wm * 32 + mi * 16 + (lane >> 2) + rr * 8;
                const size_t o = (size_t)row * HID + n0 + wn * 64 + (lane & 3) * 2;
                #pragma unroll
                for (int nj = 0; nj < 8; nj++) {
                    float2 rv = *(const float2*)(resid + o + nj * 8);
                    *(float2*)(out + o + nj * 8) =
                        make_float2(acc[mi][nj][rr*2] + b2x[nj] + rv.x,
                                    acc[mi][nj][rr*2+1] + b2y[nj] + rv.y);
                }
            }
        }
    }
}

// ==================== tensor-core flash attention (fp16) ===================
// planes (row stride 272B, 128 rows): Qh | Kh (reused as P) | Vh
#define STR  272
#define PLN  (128*STR)
#define ATT_SMEM (3*PLN)

// straight fp16 tile copy: 128 rows x 128 halves, src row stride rstride
__device__ __forceinline__ void att_cp(const __half* __restrict__ src, size_t rstride,
                                       char* dstpl, int tid)
{
    const int r = tid >> 1, c = (tid & 1) * 64;
    const __half* p = src + (size_t)r * rstride + c;
    char* d = dstpl + r * STR + c * 2;
    #pragma unroll
    for (int i = 0; i < 8; i++)
        *(uint4*)(d + i * 16) = *(const uint4*)(p + i * 8);
}

__global__ void __launch_bounds__(256, 1) attn_mma_kernel(const float* __restrict__ alibi)
{
    extern __shared__ __align__(16) char sm[];
    char* Qh = sm;
    char* Kh = sm + PLN;     // reused as P
    char* Vh = sm + 2*PLN;
    __shared__ float red_mx[2][128];
    __shared__ float red_sm[2][128];

    const int tid = threadIdx.x;
    const int wid = tid >> 5, lane = tid & 31;
    const int wm = wid >> 1, wn = wid & 1;
    const int qt = gridDim.x - 1 - blockIdx.x;
    const int bh = blockIdx.y;
    const int q0 = qt * 128;

    att_cp(g_qh + ((size_t)bh * SEQ + q0) * HD, HD, Qh, tid);

    const uint32_t a_off = (uint32_t)(wm * 32 + (lane & 15)) * STR + ((lane >> 4) << 4);
    const uint32_t b_off = (uint32_t)(wn * 64 + (lane & 7) + ((lane >> 4) << 3)) * STR
                         + (((lane >> 3) & 1) << 4);
    const uint32_t qh_b = smem_u32(Qh) + a_off;
    const uint32_t kh_b = smem_u32(Kh) + b_off;
    const uint32_t vh_b = smem_u32(Vh) + b_off;
    const uint32_t ph_b = smem_u32(Kh) + a_off;

    float o[2][8][4];
    float m_[2][2], l_[2][2], corr[2][2];
    #pragma unroll
    for (int mi = 0; mi < 2; mi++)
        #pragma unroll
        for (int rr = 0; rr < 2; rr++) { m_[mi][rr] = -1e30f; l_[mi][rr] = 0.f; }
    #pragma unroll
    for (int mi = 0; mi < 2; mi++)
        #pragma unroll
        for (int nj = 0; nj < 8; nj++)
            #pragma unroll
            for (int r = 0; r < 4; r++) o[mi][nj][r] = 0.f;

    const float* albase = alibi + (size_t)bh * SEQ;
    const int rbase = wm * 32 + (lane >> 2);

    for (int kt = 0; kt <= qt; kt++) {
        const int k0 = kt * 128;
        __syncthreads();
        att_cp(g_kh + ((size_t)bh * SEQ + k0) * HD, HD, Kh, tid);
        att_cp(g_vT + (size_t)bh * HD * SEQ + k0, SEQ, Vh, tid);
        __syncthreads();

        // S = Q K^T
        float s[2][8][4];
        #pragma unroll
        for (int mi = 0; mi < 2; mi++)
            #pragma unroll
            for (int nj = 0; nj < 8; nj++)
                #pragma unroll
                for (int r = 0; r < 4; r++) s[mi][nj][r] = 0.f;
        #pragma unroll
        for (int kk = 0; kk < 8; kk++) {
            uint32_t aH[2][4], bF[4][4];
            ldsm4(aH[0], qh_b + kk * 32);
            ldsm4(aH[1], qh_b + kk * 32 + 16 * STR);
            #pragma unroll
            for (int j2 = 0; j2 < 4; j2++) ldsm4(bF[j2], kh_b + kk * 32 + j2 * 16 * STR);
            #pragma unroll
            for (int mi = 0; mi < 2; mi++)
                #pragma unroll
                for (int j2 = 0; j2 < 4; j2++) {
                    mma16816(s[mi][2*j2],   aH[mi], &bF[j2][0]);
                    mma16816(s[mi][2*j2+1], aH[mi], &bF[j2][2]);
                }
        }

        // alibi + causal mask + partial row max
        float al[8][2];
        #pragma unroll
        for (int nj = 0; nj < 8; nj++) {
            const int col = k0 + wn * 64 + nj * 8 + (lane & 3) * 2;
            al[nj][0] = __ldg(albase + col);
            al[nj][1] = __ldg(albase + col + 1);
        }
        const bool diag = (kt == qt);
        #pragma unroll
        for (int mi = 0; mi < 2; mi++) {
            #pragma unroll
            for (int rr = 0; rr < 2; rr++) {
                const int rloc = rbase + mi * 16 + rr * 8;
                const int rowg = q0 + rloc;
                float mx = -1e30f;
                #pragma unroll
                for (int nj = 0; nj < 8; nj++) {
                    #pragma unroll
                    for (int e = 0; e < 2; e++) {
                        float v = s[mi][nj][rr*2+e] + al[nj][e];
                        if (diag && (k0 + wn*64 + nj*8 + (lane&3)*2 + e) > rowg) v = -1e30f;
                        s[mi][nj][rr*2+e] = v;
                        mx = fmaxf(mx, v);
                    }
                }
                mx = fmaxf(mx, __shfl_xor_sync(0xffffffffu, mx, 1));
                mx = fmaxf(mx, __shfl_xor_sync(0xffffffffu, mx, 2));
                if ((lane & 3) == 0) red_mx[wn][rloc] = mx;
            }
        }
        __syncthreads();

        // softmax
        #pragma unroll
        for (int mi = 0; mi < 2; mi++) {
            #pragma unroll
            for (int rr = 0; rr < 2; rr++) {
                const int rloc = rbase + mi * 16 + rr * 8;
                const float mx = fmaxf(red_mx[0][rloc], red_mx[1][rloc]);
                const float mnew = fmaxf(m_[mi][rr], mx);
                const float cr = __expf(m_[mi][rr] - mnew);
                corr[mi][rr] = cr;
                m_[mi][rr] = mnew;
                float ls = 0.f;
                #pragma unroll
                for (int nj = 0; nj < 8; nj++) {
                    #pragma unroll
                    for (int e = 0; e < 2; e++) {
                        float p = __expf(s[mi][nj][rr*2+e] - mnew);
                        s[mi][nj][rr*2+e] = p;
                        ls += p;
                    }
                }
                ls += __shfl_xor_sync(0xffffffffu, ls, 1);
                ls += __shfl_xor_sync(0xffffffffu, ls, 2);
                if ((lane & 3) == 0) red_sm[wn][rloc] = ls;
                #pragma unroll
                for (int nj = 0; nj < 8; nj++) {
                    o[mi][nj][rr*2]   *= cr;
                    o[mi][nj][rr*2+1] *= cr;
                }
            }
        }
        __syncthreads();
        #pragma unroll
        for (int mi = 0; mi < 2; mi++)
            #pragma unroll
            for (int rr = 0; rr < 2; rr++) {
                const int rloc = rbase + mi * 16 + rr * 8;
                l_[mi][rr] = l_[mi][rr] * corr[mi][rr] + red_sm[0][rloc] + red_sm[1][rloc];
            }

        // write P (fp16) into Kh plane
        #pragma unroll
        for (int mi = 0; mi < 2; mi++) {
            #pragma unroll
            for (int rr = 0; rr < 2; rr++) {
                const uint32_t roff = (uint32_t)(rbase + mi * 16 + rr * 8) * STR
                                    + (wn * 64 + (lane & 3) * 2) * 2;
                #pragma unroll
                for (int nj = 0; nj < 8; nj++)
                    *(uint32_t*)(Kh + roff + nj * 16) =
                        pack_h(s[mi][nj][rr*2], s[mi][nj][rr*2+1]);
            }
        }
        __syncthreads();

        // O += P V
        #pragma unroll
        for (int kk = 0; kk < 8; kk++) {
            uint32_t aH[2][4], bF[4][4];
            ldsm4(aH[0], ph_b + kk * 32);
            ldsm4(aH[1], ph_b + kk * 32 + 16 * STR);
            #pragma unroll
            for (int j2 = 0; j2 < 4; j2++) ldsm4(bF[j2], vh_b + kk * 32 + j2 * 16 * STR);
            #pragma unroll
            for (int mi = 0; mi < 2; mi++)
                #pragma unroll
                for (int j2 = 0; j2 < 4; j2++) {
                    mma16816(o[mi][2*j2],   aH[mi], &bF[j2][0]);
                    mma16816(o[mi][2*j2+1], aH[mi], &bF[j2][2]);
                }
        }
    }

    // epilogue -> fp16 ctx
    const int b = bh >> 5, h = bh & 31;
    #pragma unroll
    for (int mi = 0; mi < 2; mi++) {
        #pragma unroll
        for (int rr = 0; rr < 2; rr++) {
            const float invl = 1.f / l_[mi][rr];
            const int srow = q0 + rbase + mi * 16 + rr * 8;
            __half* op = g_ctxh + ((size_t)(b * SEQ + srow)) * HID + h * HD
                       + wn * 64 + (lane & 3) * 2;
            #pragma unroll
            for (int nj = 0; nj < 8; nj++)
                *(uint32_t*)(op + nj * 8) = pack_h(o[mi][nj][rr*2] * invl,
                                                   o[mi][nj][rr*2+1] * invl);
        }
    }
}

// =============================== launch ====================================
extern "C" void kernel_launch(void* const* d_in, const int* in_sizes, int n_in,
                              void* d_out, int out_size)
{
    const float* hs    = (const float*)d_in[0];
    const float* resid = (const float*)d_in[1];
    const float* alibi = (const float*)d_in[2];
    const float* Wqkv  = (const float*)d_in[4];
    const float* bqkv  = (const float*)d_in[5];
    const float* Wd    = (const float*)d_in[6];
    const float* bd    = (const float*)d_in[7];
    float* out = (float*)d_out;

    cudaFuncSetAttribute(gemm_mma_kernel<true>,
                         cudaFuncAttributeMaxDynamicSharedMemorySize, GEMM_SMEM);
    cudaFuncSetAttribute(gemm_mma_kernel<false>,
                         cudaFuncAttributeMaxDynamicSharedMemorySize, GEMM_SMEM);
    cudaFuncSetAttribute(attn_mma_kernel,
                         cudaFuncAttributeMaxDynamicSharedMemorySize, ATT_SMEM);

    __half* d_ah;    cudaGetSymbolAddress((void**)&d_ah,    g_ah);
    __half* d_wqkvT; cudaGetSymbolAddress((void**)&d_wqkvT, g_wqkvT);
    __half* d_wdT;   cudaGetSymbolAddress((void**)&d_wdT,   g_wdT);
    __half* d_ctxh;  cudaGetSymbolAddress((void**)&d_ctxh,  g_ctxh);

    // prologue converts
    conv_fp16_kernel<<<(MROWS * HID / 4 + 255) / 256, 256>>>(hs, d_ah, MROWS * HID / 4);
    transpose_fp16_kernel<<<dim3(NQKV / 32, HID / 32), dim3(32, 8)>>>(Wqkv, d_wqkvT, HID, NQKV);
    transpose_fp16_kernel<<<dim3(HID / 32, HID / 32), dim3(32, 8)>>>(Wd, d_wdT, HID, HID);

    gemm_mma_kernel<true><<<dim3(NQKV/128, MROWS/128), 256, GEMM_SMEM>>>(d_ah, d_wqkvT, bqkv, nullptr, nullptr);
    attn_mma_kernel<<<dim3(SEQ/128, BATCH*NH), 256, ATT_SMEM>>>(alibi);
    gemm_mma_kernel<false><<<dim3(HID/128, MROWS/128), 256, GEMM_SMEM>>>(d_ctxh, d_wdT, bd, resid, out);
}